// round 4
// baseline (speedup 1.0000x reference)
#include <cuda_runtime.h>
#include <math.h>

#define TOK   25088      // 8*56*56
#define CDIM  256
#define QKVN  768
#define HIDN  1024
#define HW    56
#define P2    49
#define ASCALE 0.0625f   // 256^-0.5

// ---------------- scratch (device globals; no allocation allowed) ----------
__device__ float g_h1[TOK * CDIM];            // LN output (reused for LN2)
__device__ float g_qkv[TOK * QKVN];           // qkv projections (token order)
__device__ float g_attn[TOK * CDIM];          // attention output image (+lepe)
__device__ float g_y1[TOK * CDIM];            // residual stream after attn
__device__ float g_hid[TOK * HIDN];           // MLP hidden
__device__ float g_qwin[8 * P2 * 256];
__device__ float g_kwin[8 * P2 * 256];
__device__ int   g_ridx[8 * P2 * 4];

// ---------------- helpers ---------------------------------------------------
__device__ __forceinline__ int win_token(int n, int p, int pix) {
    int wj = p / 7, wi = p % 7;
    int y = wj * 8 + (pix >> 3);
    int x = wi * 8 + (pix & 7);
    return (n * HW + y) * HW + x;
}

// exp(x) for x <= 0 on the FMA pipe (avoids MUFU throughput wall).
// 2^z split via magic-number round-to-nearest; degree-5 poly for 2^f, f in [-.5,.5].
__device__ __forceinline__ float fexp(float x) {
    float z = fmaxf(x * 1.4426950408889634f, -120.0f);
    float t = z + 12582912.0f;                       // 1.5*2^23 magic
    int   ni = __float_as_int(t) - __float_as_int(12582912.0f);
    float f = z - (t - 12582912.0f);
    float p = fmaf(f, 0.0013333558f, 0.0096181291f);
    p = fmaf(f, p, 0.0555041087f);
    p = fmaf(f, p, 0.2402265070f);
    p = fmaf(f, p, 0.6931471806f);
    p = fmaf(f, p, 1.0f);
    return p * __int_as_float((ni + 127) << 23);
}

// ---------------- LayerNorm: one warp per token -----------------------------
__global__ __launch_bounds__(256) void ln_kernel(
    const float* __restrict__ x, const float* __restrict__ g,
    const float* __restrict__ b, float* __restrict__ o)
{
    int w = blockIdx.x * 8 + (threadIdx.x >> 5);
    int lane = threadIdx.x & 31;
    const float* xp = x + (size_t)w * 256 + lane * 8;
    float4 a = *(const float4*)xp;
    float4 c = *(const float4*)(xp + 4);
    float s  = a.x + a.y + a.z + a.w + c.x + c.y + c.z + c.w;
    float ss = a.x*a.x + a.y*a.y + a.z*a.z + a.w*a.w
             + c.x*c.x + c.y*c.y + c.z*c.z + c.w*c.w;
#pragma unroll
    for (int off = 16; off; off >>= 1) {
        s  += __shfl_xor_sync(~0u, s,  off);
        ss += __shfl_xor_sync(~0u, ss, off);
    }
    float mu  = s * (1.0f / 256.0f);
    float var = ss * (1.0f / 256.0f) - mu * mu;
    float inv = rsqrtf(var + 1e-6f);
    float4 g1 = *(const float4*)(g + lane * 8);
    float4 g2 = *(const float4*)(g + lane * 8 + 4);
    float4 b1 = *(const float4*)(b + lane * 8);
    float4 b2 = *(const float4*)(b + lane * 8 + 4);
    float* op = o + (size_t)w * 256 + lane * 8;
    float4 r1, r2;
    r1.x = (a.x - mu) * inv * g1.x + b1.x;
    r1.y = (a.y - mu) * inv * g1.y + b1.y;
    r1.z = (a.z - mu) * inv * g1.z + b1.z;
    r1.w = (a.w - mu) * inv * g1.w + b1.w;
    r2.x = (c.x - mu) * inv * g2.x + b2.x;
    r2.y = (c.y - mu) * inv * g2.y + b2.y;
    r2.z = (c.z - mu) * inv * g2.z + b2.z;
    r2.w = (c.w - mu) * inv * g2.w + b2.w;
    *(float4*)op = r1;
    *(float4*)(op + 4) = r2;
}

// ---------------- generic fp32 GEMM: 64x64 tile, BK=16, 256 threads ---------
// epi: 0 = bias, 1 = bias+GELU(exact), 2 = bias + residual add
__global__ __launch_bounds__(256) void gemm_kernel(
    const float* __restrict__ A, const float* __restrict__ B,
    const float* __restrict__ bias, const float* __restrict__ res,
    float* __restrict__ Cp, int M, int N, int K, int epi)
{
    __shared__ __align__(16) float As[16][68];
    __shared__ __align__(16) float Bs[16][68];
    int tid = threadIdx.x;
    int m0 = blockIdx.y << 6, n0 = blockIdx.x << 6;
    int am = tid >> 2, ak = (tid & 3) << 2;
    int bk = tid >> 4, bn = (tid & 15) << 2;
    const float* Ap = A + (size_t)(m0 + am) * K + ak;
    const float* Bp = B + (size_t)bk * N + n0 + bn;
    int ty = tid >> 4, tx = tid & 15;
    float acc[4][4];
#pragma unroll
    for (int i = 0; i < 4; i++)
#pragma unroll
        for (int j = 0; j < 4; j++) acc[i][j] = 0.0f;

    for (int k0 = 0; k0 < K; k0 += 16) {
        float4 av = *(const float4*)(Ap + k0);
        float4 bv = *(const float4*)(Bp + (size_t)k0 * N);
        As[ak + 0][am] = av.x;
        As[ak + 1][am] = av.y;
        As[ak + 2][am] = av.z;
        As[ak + 3][am] = av.w;
        *(float4*)&Bs[bk][bn] = bv;
        __syncthreads();
#pragma unroll
        for (int kk = 0; kk < 16; kk++) {
            float4 a4 = *(float4*)&As[kk][ty << 2];
            float4 b4 = *(float4*)&Bs[kk][tx << 2];
            float aa[4] = {a4.x, a4.y, a4.z, a4.w};
            float bb[4] = {b4.x, b4.y, b4.z, b4.w};
#pragma unroll
            for (int i = 0; i < 4; i++)
#pragma unroll
                for (int j = 0; j < 4; j++)
                    acc[i][j] = fmaf(aa[i], bb[j], acc[i][j]);
        }
        __syncthreads();
    }

    float4 bias4 = *(const float4*)(bias + n0 + (tx << 2));
    float bb4[4] = {bias4.x, bias4.y, bias4.z, bias4.w};
#pragma unroll
    for (int i = 0; i < 4; i++) {
        int row = m0 + (ty << 2) + i;
        float v[4];
#pragma unroll
        for (int j = 0; j < 4; j++) v[j] = acc[i][j] + bb4[j];
        if (epi == 1) {
#pragma unroll
            for (int j = 0; j < 4; j++)
                v[j] = 0.5f * v[j] * (1.0f + erff(v[j] * 0.7071067811865476f));
        } else if (epi == 2) {
            float4 r4 = *(const float4*)(res + (size_t)row * N + n0 + (tx << 2));
            v[0] += r4.x; v[1] += r4.y; v[2] += r4.z; v[3] += r4.w;
        }
        float4 o4 = {v[0], v[1], v[2], v[3]};
        *(float4*)(Cp + (size_t)row * N + n0 + (tx << 2)) = o4;
    }
}

// ---------------- per-window q/k means --------------------------------------
__global__ __launch_bounds__(512) void winmean_kernel()
{
    int n = blockIdx.x / P2, p = blockIdx.x % P2;
    int c = threadIdx.x;   // 0..511: q channels 0..255, k channels 256..511
    float s = 0.0f;
#pragma unroll 4
    for (int pix = 0; pix < 64; pix++)
        s += g_qkv[(size_t)win_token(n, p, pix) * QKVN + c];
    s *= (1.0f / 64.0f);
    if (c < 256) g_qwin[(n * P2 + p) * 256 + c] = s;
    else         g_kwin[(n * P2 + p) * 256 + (c - 256)] = s;
}

// ---------------- routing logits + top-4 (set selection == lax.top_k set) ---
__global__ __launch_bounds__(256) void topk_kernel()
{
    int p = blockIdx.x, n = blockIdx.y;
    __shared__ float qs[256];
    __shared__ float lg[64];
    int tid = threadIdx.x;
    qs[tid] = g_qwin[(n * P2 + p) * 256 + tid];
    __syncthreads();
    if (tid < P2) {
        const float* kw = &g_kwin[(n * P2 + tid) * 256];
        float s = 0.0f;
#pragma unroll 8
        for (int cc = 0; cc < 256; cc++) s = fmaf(qs[cc], kw[cc], s);
        lg[tid] = s;
    }
    __syncthreads();
    if (tid == 0) {
        int sel[4];
        for (int t = 0; t < 4; t++) {
            float best = -1e30f; int bi = 0;
            for (int j = 0; j < P2; j++) {
                bool used = false;
                for (int u = 0; u < t; u++) if (sel[u] == j) used = true;
                float v = lg[j];
                if (!used && v > best) { best = v; bi = j; }
            }
            sel[t] = bi;
            g_ridx[(n * P2 + p) * 4 + t] = bi;
        }
    }
}

// ---------------- window attention: block per (n,p), thread = (head,query) --
__global__ __launch_bounds__(512, 1) void attn_kernel()
{
    __shared__ __align__(16) float kvs[16 * 512];  // 16 keys x (k256|v256)
    __shared__ int selw[4];
    int n = blockIdx.x / P2, p = blockIdx.x % P2;
    int tid = threadIdx.x;
    if (tid < 4) selw[tid] = g_ridx[(n * P2 + p) * 4 + tid];
    int m = tid >> 6, q = tid & 63;
    int qt = win_token(n, p, q);
    const float* qp = &g_qkv[(size_t)qt * QKVN + (m << 5)];
    float qv[32], acc[32];
#pragma unroll
    for (int d = 0; d < 32; d += 4) {
        float4 t4 = *(const float4*)(qp + d);
        qv[d] = t4.x * ASCALE; qv[d+1] = t4.y * ASCALE;
        qv[d+2] = t4.z * ASCALE; qv[d+3] = t4.w * ASCALE;
        acc[d] = 0.f; acc[d+1] = 0.f; acc[d+2] = 0.f; acc[d+3] = 0.f;
    }
    float mx = -1e30f, l = 0.0f;

    for (int chunk = 0; chunk < 16; chunk++) {
        __syncthreads();
        int sw = selw[chunk >> 2];
        int pixbase = (chunk & 3) << 4;
        // cooperative load: 16 key rows x 512 floats (k||v), coalesced float4
#pragma unroll
        for (int i = 0; i < 4; i++) {
            int idx = tid + (i << 9);            // 0..2047 float4 slots
            int row = idx >> 7, col = (idx & 127) << 2;
            int t = win_token(n, sw, pixbase + row);
            *(float4*)&kvs[(row << 9) + col] =
                *(const float4*)&g_qkv[(size_t)t * QKVN + 256 + col];
        }
        __syncthreads();

        float s[16];
#pragma unroll
        for (int kk = 0; kk < 16; kk++) {
            const float* kr = &kvs[(kk << 9) + (m << 5)];
            float t = 0.0f;
#pragma unroll
            for (int d = 0; d < 32; d++) t = fmaf(qv[d], kr[d], t);
            s[kk] = t;
        }
        float cm = s[0];
#pragma unroll
        for (int kk = 1; kk < 16; kk++) cm = fmaxf(cm, s[kk]);
        float nm = fmaxf(mx, cm);
        float corr = fexp(mx - nm);
        mx = nm;
        l *= corr;
#pragma unroll
        for (int d = 0; d < 32; d++) acc[d] *= corr;
#pragma unroll
        for (int kk = 0; kk < 16; kk++) {
            float pw = fexp(s[kk] - nm);
            l += pw;
            const float* vr = &kvs[(kk << 9) + 256 + (m << 5)];
#pragma unroll
            for (int d = 0; d < 32; d++) acc[d] = fmaf(pw, vr[d], acc[d]);
        }
    }

    float inv = 1.0f / l;
    float* op = &g_attn[(size_t)qt * 256 + (m << 5)];
#pragma unroll
    for (int d = 0; d < 32; d += 4) {
        float4 o4 = {acc[d] * inv, acc[d+1] * inv, acc[d+2] * inv, acc[d+3] * inv};
        *(float4*)(op + d) = o4;
    }
}

// ---------------- depthwise 5x5 lepe, accumulated into g_attn ---------------
__global__ __launch_bounds__(256) void lepe_kernel(
    const float* __restrict__ w, const float* __restrict__ b)
{
    int gid = blockIdx.x * 256 + threadIdx.x;   // TOK*64 c4-groups
    int t = gid >> 6;
    int c = (gid & 63) << 2;
    int n = t / 3136, rem = t % 3136, y = rem / 56, x = rem % 56;
    float4 bb = *(const float4*)(b + c);
    float av[4] = {bb.x, bb.y, bb.z, bb.w};
#pragma unroll
    for (int dy = 0; dy < 5; dy++) {
        int yy = y + dy - 2;
        if ((unsigned)yy >= 56u) continue;
#pragma unroll
        for (int dx = 0; dx < 5; dx++) {
            int xx = x + dx - 2;
            if ((unsigned)xx >= 56u) continue;
            float4 vv = *(const float4*)&g_qkv[(size_t)((n * 56 + yy) * 56 + xx) * QKVN + 512 + c];
            float4 ww = *(const float4*)(w + (dy * 5 + dx) * 256 + c);
            av[0] = fmaf(vv.x, ww.x, av[0]);
            av[1] = fmaf(vv.y, ww.y, av[1]);
            av[2] = fmaf(vv.z, ww.z, av[2]);
            av[3] = fmaf(vv.w, ww.w, av[3]);
        }
    }
    float* op = &g_attn[(size_t)t * 256 + c];
    float4 cur = *(const float4*)op;
    float4 o4 = {cur.x + av[0], cur.y + av[1], cur.z + av[2], cur.w + av[3]};
    *(float4*)op = o4;
}

// ---------------- launch ----------------------------------------------------
extern "C" void kernel_launch(void* const* d_in, const int* in_sizes, int n_in,
                              void* d_out, int out_size)
{
    const float* x     = (const float*)d_in[0];
    const float* ln1g  = (const float*)d_in[1];
    const float* ln1b  = (const float*)d_in[2];
    const float* qkvw  = (const float*)d_in[3];
    const float* qkvb  = (const float*)d_in[4];
    const float* lepew = (const float*)d_in[5];
    const float* lepeb = (const float*)d_in[6];
    const float* wow   = (const float*)d_in[7];
    const float* wob   = (const float*)d_in[8];
    const float* ln2g  = (const float*)d_in[9];
    const float* ln2b  = (const float*)d_in[10];
    const float* w1    = (const float*)d_in[11];
    const float* b1    = (const float*)d_in[12];
    const float* w2    = (const float*)d_in[13];
    const float* b2    = (const float*)d_in[14];

    float *h1, *qkv, *attn, *y1, *hid;
    cudaGetSymbolAddress((void**)&h1,   g_h1);
    cudaGetSymbolAddress((void**)&qkv,  g_qkv);
    cudaGetSymbolAddress((void**)&attn, g_attn);
    cudaGetSymbolAddress((void**)&y1,   g_y1);
    cudaGetSymbolAddress((void**)&hid,  g_hid);

    // 1. LN1
    ln_kernel<<<3136, 256>>>(x, ln1g, ln1b, h1);
    // 2. qkv projection (25088 x 768 x 256)
    gemm_kernel<<<dim3(12, 392), 256>>>(h1, qkvw, qkvb, nullptr, qkv, TOK, 768, 256, 0);
    // 3. window means for routing
    winmean_kernel<<<392, 512>>>();
    // 4. routing logits + top-4
    topk_kernel<<<dim3(49, 8), 256>>>();
    // 5. gathered window attention
    attn_kernel<<<392, 512>>>();
    // 6. lepe depthwise conv, added into attention output
    lepe_kernel<<<6272, 256>>>(lepew, lepeb);
    // 7. output projection + residual with x
    gemm_kernel<<<dim3(4, 392), 256>>>(attn, wow, wob, x, y1, TOK, 256, 256, 2);
    // 8. LN2
    ln_kernel<<<3136, 256>>>(y1, ln2g, ln2b, h1);
    // 9. MLP up + exact GELU
    gemm_kernel<<<dim3(16, 392), 256>>>(h1, w1, b1, nullptr, hid, TOK, 1024, 256, 1);
    // 10. MLP down + residual -> d_out
    gemm_kernel<<<dim3(4, 392), 256>>>(hid, w2, b2, y1, (float*)d_out, TOK, 256, 1024, 2);
}

// round 9
// speedup vs baseline: 2.3324x; 2.3324x over previous
#include <cuda_runtime.h>
#include <cuda_bf16.h>
#include <math.h>
#include <stdint.h>

#define TOK   25088      // 8*56*56
#define CDIM  256
#define QKVN  768
#define HIDN  1024
#define HW    56
#define P2    49
#define ASCALE 0.0625f   // 256^-0.5

// ---------------- scratch (device globals; no allocation allowed) ----------
__device__ __nv_bfloat16 g_h1bf[TOK * CDIM];     // LN output (bf16, GEMM A)
__device__ float         g_qkv[TOK * QKVN];      // qkv projections (fp32)
__device__ float         g_attn[TOK * CDIM];     // attention output (+lepe)
__device__ __nv_bfloat16 g_attnbf[TOK * CDIM];   // bf16 copy for wo GEMM
__device__ float         g_y1[TOK * CDIM];       // residual stream after attn
__device__ __nv_bfloat16 g_hidbf[TOK * HIDN];    // MLP hidden (bf16, from epi)
// transposed bf16 weights, concatenated: [N x K] layouts
#define WT_QKV 0
#define WT_WO  (768*256)
#define WT_W1  (WT_WO + 256*256)
#define WT_W2  (WT_W1 + 1024*256)
__device__ __nv_bfloat16 g_wt[768*256 + 256*256 + 1024*256 + 256*1024];
__device__ float g_qwin[8 * P2 * 256];
__device__ float g_kwin[8 * P2 * 256];
__device__ int   g_ridx[8 * P2 * 4];

// ---------------- small helpers ---------------------------------------------
__device__ __forceinline__ uint32_t smem_u32(const void* p) {
    uint32_t a;
    asm("{ .reg .u64 t; cvta.to.shared.u64 t, %1; cvt.u32.u64 %0, t; }"
        : "=r"(a) : "l"(p));
    return a;
}
#define CPA16(dst, src) \
    asm volatile("cp.async.cg.shared.global [%0], [%1], 16;" :: "r"(dst), "l"(src))
#define CPA_COMMIT() asm volatile("cp.async.commit_group;" ::: "memory")

__device__ __forceinline__ void mma_bf16(float* c, const uint32_t* a, const uint32_t* b) {
    asm volatile(
        "mma.sync.aligned.m16n8k16.row.col.f32.bf16.bf16.f32 "
        "{%0,%1,%2,%3}, {%4,%5,%6,%7}, {%8,%9}, {%0,%1,%2,%3};"
        : "+f"(c[0]), "+f"(c[1]), "+f"(c[2]), "+f"(c[3])
        : "r"(a[0]), "r"(a[1]), "r"(a[2]), "r"(a[3]), "r"(b[0]), "r"(b[1]));
}

__device__ __forceinline__ uint32_t pack_bf2(float v0, float v1) {
    __nv_bfloat162 pk = __floats2bfloat162_rn(v0, v1);
    uint32_t r;
    *(__nv_bfloat162*)&r = pk;
    return r;
}

// ---------------- bf16 HMMA GEMM: 128x64 tile, BK=32, cp.async 2-stage ------
// A: [M,K] bf16 row-major.  Bt: [N,K] bf16 row-major (pre-transposed weight).
// epi: 0 = bias (fp32 out), 1 = bias+GELU (bf16 out), 2 = bias+res (fp32 out)
#define SROW 40   // smem row stride in bf16 (80B) -> conflict-free frag loads
__global__ __launch_bounds__(256) void gemm_mma_kernel(
    const __nv_bfloat16* __restrict__ A, const __nv_bfloat16* __restrict__ Bt,
    const float* __restrict__ bias, const float* __restrict__ res,
    float* __restrict__ Cf, __nv_bfloat16* __restrict__ Cb,
    int M, int N, int K, int epi)
{
    __shared__ __align__(16) __nv_bfloat16 sa[2][128][SROW];
    __shared__ __align__(16) __nv_bfloat16 sb[2][64][SROW];

    const int tid = threadIdx.x;
    const int wid = tid >> 5, l = tid & 31;
    const int wm = wid >> 1, wn = wid & 1;            // warp grid 4x2
    const int m0 = blockIdx.y << 7, n0 = blockIdx.x << 6;
    const int gr = l >> 2, tc = (l & 3) << 1;

    // global-load mapping: thread covers A rows (tid>>2, tid>>2+64), B row tid>>2,
    // 8 bf16 (16B) at col (tid&3)*8 of the 32-wide K slice.
    const int lr = tid >> 2, lc = (tid & 3) << 3;
    const __nv_bfloat16* Ap0 = A + (size_t)(m0 + lr) * K + lc;
    const __nv_bfloat16* Ap1 = A + (size_t)(m0 + lr + 64) * K + lc;
    const __nv_bfloat16* Bp  = Bt + (size_t)(n0 + lr) * K + lc;
    const uint32_t sa0 = smem_u32(&sa[0][lr][lc]);
    const uint32_t sa1 = smem_u32(&sa[0][lr + 64][lc]);
    const uint32_t sb0 = smem_u32(&sb[0][lr][lc]);
    const uint32_t ABUF = 128 * SROW * 2, BBUF = 64 * SROW * 2;

    float acc[2][4][4];
#pragma unroll
    for (int i = 0; i < 2; i++)
#pragma unroll
        for (int j = 0; j < 4; j++)
#pragma unroll
            for (int v = 0; v < 4; v++) acc[i][j][v] = 0.0f;

    const int nst = K >> 5;
    // prologue: stage 0 -> buf 0
    CPA16(sa0, Ap0); CPA16(sa1, Ap1); CPA16(sb0, Bp);
    CPA_COMMIT();

    int buf = 0;
    for (int s = 0; s < nst; s++) {
        if (s + 1 < nst) {
            int k0 = (s + 1) << 5;
            int ob = (buf ^ 1);
            CPA16(sa0 + ob * ABUF, Ap0 + k0);
            CPA16(sa1 + ob * ABUF, Ap1 + k0);
            CPA16(sb0 + ob * BBUF, Bp + k0);
            CPA_COMMIT();
            asm volatile("cp.async.wait_group 1;" ::: "memory");
        } else {
            asm volatile("cp.async.wait_group 0;" ::: "memory");
        }
        __syncthreads();

#pragma unroll
        for (int kk = 0; kk < 32; kk += 16) {
            uint32_t af[2][4], bfr[4][2];
#pragma unroll
            for (int mi = 0; mi < 2; mi++) {
                int r = (wm << 5) + (mi << 4) + gr;
                af[mi][0] = *(const uint32_t*)&sa[buf][r][kk + tc];
                af[mi][1] = *(const uint32_t*)&sa[buf][r + 8][kk + tc];
                af[mi][2] = *(const uint32_t*)&sa[buf][r][kk + tc + 8];
                af[mi][3] = *(const uint32_t*)&sa[buf][r + 8][kk + tc + 8];
            }
#pragma unroll
            for (int ni = 0; ni < 4; ni++) {
                int r = (wn << 5) + (ni << 3) + gr;
                bfr[ni][0] = *(const uint32_t*)&sb[buf][r][kk + tc];
                bfr[ni][1] = *(const uint32_t*)&sb[buf][r][kk + tc + 8];
            }
#pragma unroll
            for (int mi = 0; mi < 2; mi++)
#pragma unroll
                for (int ni = 0; ni < 4; ni++)
                    mma_bf16(acc[mi][ni], af[mi], bfr[ni]);
        }
        __syncthreads();
        buf ^= 1;
    }

    // ---------------- epilogue ----------------
    float2 bv[4];
#pragma unroll
    for (int ni = 0; ni < 4; ni++)
        bv[ni] = *(const float2*)(bias + n0 + (wn << 5) + (ni << 3) + tc);

#pragma unroll
    for (int mi = 0; mi < 2; mi++) {
#pragma unroll
        for (int h = 0; h < 2; h++) {          // row halves (+0 / +8)
            int row = m0 + (wm << 5) + (mi << 4) + gr + (h << 3);
#pragma unroll
            for (int ni = 0; ni < 4; ni++) {
                int col = n0 + (wn << 5) + (ni << 3) + tc;
                float v0 = acc[mi][ni][h * 2 + 0] + bv[ni].x;
                float v1 = acc[mi][ni][h * 2 + 1] + bv[ni].y;
                if (epi == 1) {
                    v0 = 0.5f * v0 * (1.0f + erff(v0 * 0.7071067811865476f));
                    v1 = 0.5f * v1 * (1.0f + erff(v1 * 0.7071067811865476f));
                    *(uint32_t*)(Cb + (size_t)row * N + col) = pack_bf2(v0, v1);
                } else {
                    if (epi == 2) {
                        float2 r2 = *(const float2*)(res + (size_t)row * N + col);
                        v0 += r2.x; v1 += r2.y;
                    }
                    float2 o2;
                    o2.x = v0; o2.y = v1;
                    *(float2*)(Cf + (size_t)row * N + col) = o2;
                }
            }
        }
    }
}

// ---------------- helpers ---------------------------------------------------
__device__ __forceinline__ int win_token(int n, int p, int pix) {
    int wj = p / 7, wi = p % 7;
    int y = wj * 8 + (pix >> 3);
    int x = wi * 8 + (pix & 7);
    return (n * HW + y) * HW + x;
}

// exp(x) for x <= 0 on the FMA pipe (avoids MUFU throughput wall).
__device__ __forceinline__ float fexp(float x) {
    float z = fmaxf(x * 1.4426950408889634f, -120.0f);
    float t = z + 12582912.0f;                       // 1.5*2^23 magic
    int   ni = __float_as_int(t) - __float_as_int(12582912.0f);
    float f = z - (t - 12582912.0f);
    float p = fmaf(f, 0.0013333558f, 0.0096181291f);
    p = fmaf(f, p, 0.0555041087f);
    p = fmaf(f, p, 0.2402265070f);
    p = fmaf(f, p, 0.6931471806f);
    p = fmaf(f, p, 1.0f);
    return p * __int_as_float((ni + 127) << 23);
}

// ---------------- LayerNorm: one warp per token, bf16 output ----------------
__global__ __launch_bounds__(256) void ln_bf_kernel(
    const float* __restrict__ x, const float* __restrict__ g,
    const float* __restrict__ b, __nv_bfloat16* __restrict__ o)
{
    int w = blockIdx.x * 8 + (threadIdx.x >> 5);
    int lane = threadIdx.x & 31;
    const float* xp = x + (size_t)w * 256 + lane * 8;
    float4 a = *(const float4*)xp;
    float4 c = *(const float4*)(xp + 4);
    float s  = a.x + a.y + a.z + a.w + c.x + c.y + c.z + c.w;
    float ss = a.x*a.x + a.y*a.y + a.z*a.z + a.w*a.w
             + c.x*c.x + c.y*c.y + c.z*c.z + c.w*c.w;
#pragma unroll
    for (int off = 16; off; off >>= 1) {
        s  += __shfl_xor_sync(~0u, s,  off);
        ss += __shfl_xor_sync(~0u, ss, off);
    }
    float mu  = s * (1.0f / 256.0f);
    float var = ss * (1.0f / 256.0f) - mu * mu;
    float inv = rsqrtf(var + 1e-6f);
    float4 g1 = *(const float4*)(g + lane * 8);
    float4 g2 = *(const float4*)(g + lane * 8 + 4);
    float4 b1 = *(const float4*)(b + lane * 8);
    float4 b2 = *(const float4*)(b + lane * 8 + 4);
    float v[8];
    v[0] = (a.x - mu) * inv * g1.x + b1.x;
    v[1] = (a.y - mu) * inv * g1.y + b1.y;
    v[2] = (a.z - mu) * inv * g1.z + b1.z;
    v[3] = (a.w - mu) * inv * g1.w + b1.w;
    v[4] = (c.x - mu) * inv * g2.x + b2.x;
    v[5] = (c.y - mu) * inv * g2.y + b2.y;
    v[6] = (c.z - mu) * inv * g2.z + b2.z;
    v[7] = (c.w - mu) * inv * g2.w + b2.w;
    uint32_t pk[4];
#pragma unroll
    for (int j = 0; j < 4; j++) pk[j] = pack_bf2(v[2*j], v[2*j+1]);
    *(uint4*)(o + (size_t)w * 256 + lane * 8) = *(uint4*)pk;
}

// ---------------- fp32 -> bf16 convert (8 elems / thread) -------------------
__global__ __launch_bounds__(256) void cvt_bf_kernel(
    const float* __restrict__ in, __nv_bfloat16* __restrict__ out)
{
    size_t gid = (size_t)blockIdx.x * 256 + threadIdx.x;
    const float* ip = in + gid * 8;
    float4 a = *(const float4*)ip;
    float4 c = *(const float4*)(ip + 4);
    uint32_t pk[4];
    pk[0] = pack_bf2(a.x, a.y);
    pk[1] = pack_bf2(a.z, a.w);
    pk[2] = pack_bf2(c.x, c.y);
    pk[3] = pack_bf2(c.z, c.w);
    *(uint4*)(out + gid * 8) = *(uint4*)pk;
}

// ---------------- weight transpose+convert: w[K][N] -> o[N][K] bf16 ---------
__global__ __launch_bounds__(256) void wtrans_kernel(
    const float* __restrict__ w, __nv_bfloat16* __restrict__ o, int K, int N)
{
    int gid = blockIdx.x * 256 + threadIdx.x;   // over N*K outputs
    int n = gid / K, k = gid % K;
    o[gid] = __float2bfloat16_rn(w[(size_t)k * N + n]);
}

// ---------------- per-window q/k means --------------------------------------
__global__ __launch_bounds__(512) void winmean_kernel()
{
    int n = blockIdx.x / P2, p = blockIdx.x % P2;
    int c = threadIdx.x;   // 0..511: q channels 0..255, k channels 256..511
    float s = 0.0f;
#pragma unroll 4
    for (int pix = 0; pix < 64; pix++)
        s += g_qkv[(size_t)win_token(n, p, pix) * QKVN + c];
    s *= (1.0f / 64.0f);
    if (c < 256) g_qwin[(n * P2 + p) * 256 + c] = s;
    else         g_kwin[(n * P2 + p) * 256 + (c - 256)] = s;
}

// ---------------- routing logits + top-4 (set selection == lax.top_k set) ---
__global__ __launch_bounds__(256) void topk_kernel()
{
    int p = blockIdx.x, n = blockIdx.y;
    __shared__ float qs[256];
    __shared__ float lg[64];
    int tid = threadIdx.x;
    qs[tid] = g_qwin[(n * P2 + p) * 256 + tid];
    __syncthreads();
    if (tid < P2) {
        const float* kw = &g_kwin[(n * P2 + tid) * 256];
        float s = 0.0f;
#pragma unroll 8
        for (int cc = 0; cc < 256; cc++) s = fmaf(qs[cc], kw[cc], s);
        lg[tid] = s;
    }
    __syncthreads();
    if (tid == 0) {
        int sel[4];
        for (int t = 0; t < 4; t++) {
            float best = -1e30f; int bi = 0;
            for (int j = 0; j < P2; j++) {
                bool used = false;
                for (int u = 0; u < t; u++) if (sel[u] == j) used = true;
                float v = lg[j];
                if (!used && v > best) { best = v; bi = j; }
            }
            sel[t] = bi;
            g_ridx[(n * P2 + p) * 4 + t] = bi;
        }
    }
}

// ---------------- window attention: block per (n,p), thread = (head,query) --
__global__ __launch_bounds__(512, 1) void attn_kernel()
{
    __shared__ __align__(16) float kvs[16 * 512];  // 16 keys x (k256|v256)
    __shared__ int selw[4];
    int n = blockIdx.x / P2, p = blockIdx.x % P2;
    int tid = threadIdx.x;
    if (tid < 4) selw[tid] = g_ridx[(n * P2 + p) * 4 + tid];
    int m = tid >> 6, q = tid & 63;
    int qt = win_token(n, p, q);
    const float* qp = &g_qkv[(size_t)qt * QKVN + (m << 5)];
    float qv[32], acc[32];
#pragma unroll
    for (int d = 0; d < 32; d += 4) {
        float4 t4 = *(const float4*)(qp + d);
        qv[d] = t4.x * ASCALE; qv[d+1] = t4.y * ASCALE;
        qv[d+2] = t4.z * ASCALE; qv[d+3] = t4.w * ASCALE;
        acc[d] = 0.f; acc[d+1] = 0.f; acc[d+2] = 0.f; acc[d+3] = 0.f;
    }
    float mx = -1e30f, l = 0.0f;

    for (int chunk = 0; chunk < 16; chunk++) {
        __syncthreads();
        int sw = selw[chunk >> 2];
        int pixbase = (chunk & 3) << 4;
#pragma unroll
        for (int i = 0; i < 4; i++) {
            int idx = tid + (i << 9);            // 0..2047 float4 slots
            int row = idx >> 7, col = (idx & 127) << 2;
            int t = win_token(n, sw, pixbase + row);
            *(float4*)&kvs[(row << 9) + col] =
                *(const float4*)&g_qkv[(size_t)t * QKVN + 256 + col];
        }
        __syncthreads();

        float s[16];
#pragma unroll
        for (int kk = 0; kk < 16; kk++) {
            const float* kr = &kvs[(kk << 9) + (m << 5)];
            float t = 0.0f;
#pragma unroll
            for (int d = 0; d < 32; d++) t = fmaf(qv[d], kr[d], t);
            s[kk] = t;
        }
        float cm = s[0];
#pragma unroll
        for (int kk = 1; kk < 16; kk++) cm = fmaxf(cm, s[kk]);
        float nm = fmaxf(mx, cm);
        float corr = fexp(mx - nm);
        mx = nm;
        l *= corr;
#pragma unroll
        for (int d = 0; d < 32; d++) acc[d] *= corr;
#pragma unroll
        for (int kk = 0; kk < 16; kk++) {
            float pw = fexp(s[kk] - nm);
            l += pw;
            const float* vr = &kvs[(kk << 9) + 256 + (m << 5)];
#pragma unroll
            for (int d = 0; d < 32; d++) acc[d] = fmaf(pw, vr[d], acc[d]);
        }
    }

    float inv = 1.0f / l;
    float* op = &g_attn[(size_t)qt * 256 + (m << 5)];
#pragma unroll
    for (int d = 0; d < 32; d += 4) {
        float4 o4 = {acc[d] * inv, acc[d+1] * inv, acc[d+2] * inv, acc[d+3] * inv};
        *(float4*)(op + d) = o4;
    }
}

// ---------------- depthwise 5x5 lepe, accumulated into g_attn ---------------
__global__ __launch_bounds__(256) void lepe_kernel(
    const float* __restrict__ w, const float* __restrict__ b)
{
    int gid = blockIdx.x * 256 + threadIdx.x;   // TOK*64 c4-groups
    int t = gid >> 6;
    int c = (gid & 63) << 2;
    int n = t / 3136, rem = t % 3136, y = rem / 56, x = rem % 56;
    float4 bb = *(const float4*)(b + c);
    float av[4] = {bb.x, bb.y, bb.z, bb.w};
#pragma unroll
    for (int dy = 0; dy < 5; dy++) {
        int yy = y + dy - 2;
        if ((unsigned)yy >= 56u) continue;
#pragma unroll
        for (int dx = 0; dx < 5; dx++) {
            int xx = x + dx - 2;
            if ((unsigned)xx >= 56u) continue;
            float4 vv = *(const float4*)&g_qkv[(size_t)((n * 56 + yy) * 56 + xx) * QKVN + 512 + c];
            float4 ww = *(const float4*)(w + (dy * 5 + dx) * 256 + c);
            av[0] = fmaf(vv.x, ww.x, av[0]);
            av[1] = fmaf(vv.y, ww.y, av[1]);
            av[2] = fmaf(vv.z, ww.z, av[2]);
            av[3] = fmaf(vv.w, ww.w, av[3]);
        }
    }
    float* op = &g_attn[(size_t)t * 256 + c];
    float4 cur = *(const float4*)op;
    float4 o4 = {cur.x + av[0], cur.y + av[1], cur.z + av[2], cur.w + av[3]};
    *(float4*)op = o4;
}

// ---------------- launch ----------------------------------------------------
extern "C" void kernel_launch(void* const* d_in, const int* in_sizes, int n_in,
                              void* d_out, int out_size)
{
    const float* x     = (const float*)d_in[0];
    const float* ln1g  = (const float*)d_in[1];
    const float* ln1b  = (const float*)d_in[2];
    const float* qkvw  = (const float*)d_in[3];
    const float* qkvb  = (const float*)d_in[4];
    const float* lepew = (const float*)d_in[5];
    const float* lepeb = (const float*)d_in[6];
    const float* wow   = (const float*)d_in[7];
    const float* wob   = (const float*)d_in[8];
    const float* ln2g  = (const float*)d_in[9];
    const float* ln2b  = (const float*)d_in[10];
    const float* w1    = (const float*)d_in[11];
    const float* b1    = (const float*)d_in[12];
    const float* w2    = (const float*)d_in[13];
    const float* b2    = (const float*)d_in[14];

    __nv_bfloat16 *h1bf, *attnbf, *hidbf, *wt;
    float *qkv, *attn, *y1;
    cudaGetSymbolAddress((void**)&h1bf,   g_h1bf);
    cudaGetSymbolAddress((void**)&qkv,    g_qkv);
    cudaGetSymbolAddress((void**)&attn,   g_attn);
    cudaGetSymbolAddress((void**)&attnbf, g_attnbf);
    cudaGetSymbolAddress((void**)&y1,     g_y1);
    cudaGetSymbolAddress((void**)&hidbf,  g_hidbf);
    cudaGetSymbolAddress((void**)&wt,     g_wt);

    // weight transpose+convert (tiny)
    wtrans_kernel<<<768 * 256 / 256, 256>>>(qkvw, wt + WT_QKV, 256, 768);
    wtrans_kernel<<<256 * 256 / 256, 256>>>(wow,  wt + WT_WO,  256, 256);
    wtrans_kernel<<<1024 * 256 / 256, 256>>>(w1,  wt + WT_W1,  256, 1024);
    wtrans_kernel<<<256 * 1024 / 256, 256>>>(w2,  wt + WT_W2,  1024, 256);

    // 1. LN1 -> bf16
    ln_bf_kernel<<<3136, 256>>>(x, ln1g, ln1b, h1bf);
    // 2. qkv projection (25088 x 768 x 256), HMMA
    gemm_mma_kernel<<<dim3(12, 196), 256>>>(h1bf, wt + WT_QKV, qkvb, nullptr,
                                            qkv, nullptr, TOK, 768, 256, 0);
    // 3-4. routing
    winmean_kernel<<<392, 512>>>();
    topk_kernel<<<dim3(49, 8), 256>>>();
    // 5. gathered window attention
    attn_kernel<<<392, 512>>>();
    // 6. lepe depthwise conv, added into attention output
    lepe_kernel<<<6272, 256>>>(lepew, lepeb);
    // 6b. attn -> bf16
    cvt_bf_kernel<<<TOK * CDIM / (256 * 8), 256>>>(attn, attnbf);
    // 7. output projection + residual with x
    gemm_mma_kernel<<<dim3(4, 196), 256>>>(attnbf, wt + WT_WO, wob, x,
                                           y1, nullptr, TOK, 256, 256, 2);
    // 8. LN2 -> bf16
    ln_bf_kernel<<<3136, 256>>>(y1, ln2g, ln2b, h1bf);
    // 9. MLP up + exact GELU, bf16 out
    gemm_mma_kernel<<<dim3(16, 196), 256>>>(h1bf, wt + WT_W1, b1, nullptr,
                                            nullptr, hidbf, TOK, 1024, 256, 1);
    // 10. MLP down + residual -> d_out
    gemm_mma_kernel<<<dim3(4, 196), 256>>>(hidbf, wt + WT_W2, b2, y1,
                                           (float*)d_out, nullptr, TOK, 256, 1024, 2);
}

// round 10
// speedup vs baseline: 3.2306x; 1.3851x over previous
#include <cuda_runtime.h>
#include <cuda_fp16.h>
#include <math.h>
#include <stdint.h>

#define TOK   25088      // 8*56*56
#define CDIM  256
#define QKVN  768
#define HIDN  1024
#define HW    56
#define P2    49
#define ASCALE 0.0625f   // 256^-0.5

// ---------------- scratch (device globals; no allocation allowed) ----------
__device__ __half g_h1h[TOK * CDIM];      // LN output (fp16, GEMM A)
__device__ float  g_qkv[TOK * QKVN];      // qkv projections (fp32: routing+lepe)
__device__ __half g_qkvh[TOK * QKVN];     // fp16 copy (attention operands)
__device__ float  g_attn[TOK * CDIM];     // attention output fp32 (pre-lepe)
__device__ __half g_attnh[TOK * CDIM];    // attn+lepe, fp16 (wo GEMM A)
__device__ float  g_y1[TOK * CDIM];       // residual stream after attn
__device__ __half g_hidh[TOK * HIDN];     // MLP hidden (fp16, from epi)
// transposed fp16 weights, concatenated: [N x K] layouts
#define WT_QKV 0
#define WT_WO  (768*256)
#define WT_W1  (WT_WO + 256*256)
#define WT_W2  (WT_W1 + 1024*256)
__device__ __half g_wt[768*256 + 256*256 + 1024*256 + 256*1024];
__device__ float g_qwin[8 * P2 * 256];
__device__ float g_kwin[8 * P2 * 256];
__device__ int   g_ridx[8 * P2 * 4];

// ---------------- small helpers ---------------------------------------------
__device__ __forceinline__ uint32_t smem_u32(const void* p) {
    uint32_t a;
    asm("{ .reg .u64 t; cvta.to.shared.u64 t, %1; cvt.u32.u64 %0, t; }"
        : "=r"(a) : "l"(p));
    return a;
}
#define CPA16(dst, src) \
    asm volatile("cp.async.cg.shared.global [%0], [%1], 16;" :: "r"(dst), "l"(src))
#define CPA_COMMIT() asm volatile("cp.async.commit_group;" ::: "memory")

__device__ __forceinline__ void mma_f16(float* c, const uint32_t* a, const uint32_t* b) {
    asm volatile(
        "mma.sync.aligned.m16n8k16.row.col.f32.f16.f16.f32 "
        "{%0,%1,%2,%3}, {%4,%5,%6,%7}, {%8,%9}, {%0,%1,%2,%3};"
        : "+f"(c[0]), "+f"(c[1]), "+f"(c[2]), "+f"(c[3])
        : "r"(a[0]), "r"(a[1]), "r"(a[2]), "r"(a[3]), "r"(b[0]), "r"(b[1]));
}

__device__ __forceinline__ uint32_t pack_h2(float v0, float v1) {
    __half2 pk = __floats2half2_rn(v0, v1);
    uint32_t r;
    *(__half2*)&r = pk;
    return r;
}

// ---------------- fp16 HMMA GEMM: 128x64 tile, BK=32, cp.async 2-stage ------
// A: [M,K] fp16 row-major.  Bt: [N,K] fp16 row-major (pre-transposed weight).
// epi: 0 = bias (fp32 out + optional fp16 copy), 1 = bias+GELU (fp16 out),
//      2 = bias + residual (fp32 out)
#define SROW 40   // smem row stride in halves (80B) -> conflict-free frag loads
__global__ __launch_bounds__(256) void gemm_mma_kernel(
    const __half* __restrict__ A, const __half* __restrict__ Bt,
    const float* __restrict__ bias, const float* __restrict__ res,
    float* __restrict__ Cf, __half* __restrict__ Ch,
    int M, int N, int K, int epi)
{
    __shared__ __align__(16) __half sa[2][128][SROW];
    __shared__ __align__(16) __half sb[2][64][SROW];

    const int tid = threadIdx.x;
    const int wid = tid >> 5, l = tid & 31;
    const int wm = wid >> 1, wn = wid & 1;            // warp grid 4x2
    const int m0 = blockIdx.y << 7, n0 = blockIdx.x << 6;
    const int gr = l >> 2, tc = (l & 3) << 1;

    const int lr = tid >> 2, lc = (tid & 3) << 3;
    const __half* Ap0 = A + (size_t)(m0 + lr) * K + lc;
    const __half* Ap1 = A + (size_t)(m0 + lr + 64) * K + lc;
    const __half* Bp  = Bt + (size_t)(n0 + lr) * K + lc;
    const uint32_t sa0 = smem_u32(&sa[0][lr][lc]);
    const uint32_t sa1 = smem_u32(&sa[0][lr + 64][lc]);
    const uint32_t sb0 = smem_u32(&sb[0][lr][lc]);
    const uint32_t ABUF = 128 * SROW * 2, BBUF = 64 * SROW * 2;

    float acc[2][4][4];
#pragma unroll
    for (int i = 0; i < 2; i++)
#pragma unroll
        for (int j = 0; j < 4; j++)
#pragma unroll
            for (int v = 0; v < 4; v++) acc[i][j][v] = 0.0f;

    const int nst = K >> 5;
    CPA16(sa0, Ap0); CPA16(sa1, Ap1); CPA16(sb0, Bp);
    CPA_COMMIT();

    int buf = 0;
    for (int s = 0; s < nst; s++) {
        if (s + 1 < nst) {
            int k0 = (s + 1) << 5;
            int ob = (buf ^ 1);
            CPA16(sa0 + ob * ABUF, Ap0 + k0);
            CPA16(sa1 + ob * ABUF, Ap1 + k0);
            CPA16(sb0 + ob * BBUF, Bp + k0);
            CPA_COMMIT();
            asm volatile("cp.async.wait_group 1;" ::: "memory");
        } else {
            asm volatile("cp.async.wait_group 0;" ::: "memory");
        }
        __syncthreads();

#pragma unroll
        for (int kk = 0; kk < 32; kk += 16) {
            uint32_t af[2][4], bfr[4][2];
#pragma unroll
            for (int mi = 0; mi < 2; mi++) {
                int r = (wm << 5) + (mi << 4) + gr;
                af[mi][0] = *(const uint32_t*)&sa[buf][r][kk + tc];
                af[mi][1] = *(const uint32_t*)&sa[buf][r + 8][kk + tc];
                af[mi][2] = *(const uint32_t*)&sa[buf][r][kk + tc + 8];
                af[mi][3] = *(const uint32_t*)&sa[buf][r + 8][kk + tc + 8];
            }
#pragma unroll
            for (int ni = 0; ni < 4; ni++) {
                int r = (wn << 5) + (ni << 3) + gr;
                bfr[ni][0] = *(const uint32_t*)&sb[buf][r][kk + tc];
                bfr[ni][1] = *(const uint32_t*)&sb[buf][r][kk + tc + 8];
            }
#pragma unroll
            for (int mi = 0; mi < 2; mi++)
#pragma unroll
                for (int ni = 0; ni < 4; ni++)
                    mma_f16(acc[mi][ni], af[mi], bfr[ni]);
        }
        __syncthreads();
        buf ^= 1;
    }

    // ---------------- epilogue ----------------
    float2 bv[4];
#pragma unroll
    for (int ni = 0; ni < 4; ni++)
        bv[ni] = *(const float2*)(bias + n0 + (wn << 5) + (ni << 3) + tc);

#pragma unroll
    for (int mi = 0; mi < 2; mi++) {
#pragma unroll
        for (int h = 0; h < 2; h++) {          // row halves (+0 / +8)
            int row = m0 + (wm << 5) + (mi << 4) + gr + (h << 3);
#pragma unroll
            for (int ni = 0; ni < 4; ni++) {
                int col = n0 + (wn << 5) + (ni << 3) + tc;
                float v0 = acc[mi][ni][h * 2 + 0] + bv[ni].x;
                float v1 = acc[mi][ni][h * 2 + 1] + bv[ni].y;
                if (epi == 1) {
                    v0 = 0.5f * v0 * (1.0f + erff(v0 * 0.7071067811865476f));
                    v1 = 0.5f * v1 * (1.0f + erff(v1 * 0.7071067811865476f));
                    *(uint32_t*)(Ch + (size_t)row * N + col) = pack_h2(v0, v1);
                } else {
                    if (epi == 2) {
                        float2 r2 = *(const float2*)(res + (size_t)row * N + col);
                        v0 += r2.x; v1 += r2.y;
                    }
                    float2 o2;
                    o2.x = v0; o2.y = v1;
                    *(float2*)(Cf + (size_t)row * N + col) = o2;
                    if (epi == 0 && Ch)
                        *(uint32_t*)(Ch + (size_t)row * N + col) = pack_h2(v0, v1);
                }
            }
        }
    }
}

// ---------------- helpers ---------------------------------------------------
__device__ __forceinline__ int win_token(int n, int p, int pix) {
    int wj = p / 7, wi = p % 7;
    int y = wj * 8 + (pix >> 3);
    int x = wi * 8 + (pix & 7);
    return (n * HW + y) * HW + x;
}

// exp(x) for x <= 0 on the FMA pipe (avoids MUFU throughput wall).
__device__ __forceinline__ float fexp(float x) {
    float z = fmaxf(x * 1.4426950408889634f, -120.0f);
    float t = z + 12582912.0f;                       // 1.5*2^23 magic
    int   ni = __float_as_int(t) - __float_as_int(12582912.0f);
    float f = z - (t - 12582912.0f);
    float p = fmaf(f, 0.0013333558f, 0.0096181291f);
    p = fmaf(f, p, 0.0555041087f);
    p = fmaf(f, p, 0.2402265070f);
    p = fmaf(f, p, 0.6931471806f);
    p = fmaf(f, p, 1.0f);
    return p * __int_as_float((ni + 127) << 23);
}

// ---------------- LayerNorm: one warp per token, fp16 output ----------------
__global__ __launch_bounds__(256) void ln_h_kernel(
    const float* __restrict__ x, const float* __restrict__ g,
    const float* __restrict__ b, __half* __restrict__ o)
{
    int w = blockIdx.x * 8 + (threadIdx.x >> 5);
    int lane = threadIdx.x & 31;
    const float* xp = x + (size_t)w * 256 + lane * 8;
    float4 a = *(const float4*)xp;
    float4 c = *(const float4*)(xp + 4);
    float s  = a.x + a.y + a.z + a.w + c.x + c.y + c.z + c.w;
    float ss = a.x*a.x + a.y*a.y + a.z*a.z + a.w*a.w
             + c.x*c.x + c.y*c.y + c.z*c.z + c.w*c.w;
#pragma unroll
    for (int off = 16; off; off >>= 1) {
        s  += __shfl_xor_sync(~0u, s,  off);
        ss += __shfl_xor_sync(~0u, ss, off);
    }
    float mu  = s * (1.0f / 256.0f);
    float var = ss * (1.0f / 256.0f) - mu * mu;
    float inv = rsqrtf(var + 1e-6f);
    float4 g1 = *(const float4*)(g + lane * 8);
    float4 g2 = *(const float4*)(g + lane * 8 + 4);
    float4 b1 = *(const float4*)(b + lane * 8);
    float4 b2 = *(const float4*)(b + lane * 8 + 4);
    float v[8];
    v[0] = (a.x - mu) * inv * g1.x + b1.x;
    v[1] = (a.y - mu) * inv * g1.y + b1.y;
    v[2] = (a.z - mu) * inv * g1.z + b1.z;
    v[3] = (a.w - mu) * inv * g1.w + b1.w;
    v[4] = (c.x - mu) * inv * g2.x + b2.x;
    v[5] = (c.y - mu) * inv * g2.y + b2.y;
    v[6] = (c.z - mu) * inv * g2.z + b2.z;
    v[7] = (c.w - mu) * inv * g2.w + b2.w;
    uint32_t pk[4];
#pragma unroll
    for (int j = 0; j < 4; j++) pk[j] = pack_h2(v[2*j], v[2*j+1]);
    *(uint4*)(o + (size_t)w * 256 + lane * 8) = *(uint4*)pk;
}

// ---------------- weight transpose+convert: w[K][N] -> o[N][K] fp16 ---------
__global__ __launch_bounds__(256) void wtrans_kernel(
    const float* __restrict__ w, __half* __restrict__ o, int K, int N)
{
    int gid = blockIdx.x * 256 + threadIdx.x;   // over N*K outputs
    int n = gid / K, k = gid % K;
    o[gid] = __float2half_rn(w[(size_t)k * N + n]);
}

// ---------------- per-window q/k means --------------------------------------
__global__ __launch_bounds__(512) void winmean_kernel()
{
    int n = blockIdx.x / P2, p = blockIdx.x % P2;
    int c = threadIdx.x;   // 0..511: q channels 0..255, k channels 256..511
    float s = 0.0f;
#pragma unroll 4
    for (int pix = 0; pix < 64; pix++)
        s += g_qkv[(size_t)win_token(n, p, pix) * QKVN + c];
    s *= (1.0f / 64.0f);
    if (c < 256) g_qwin[(n * P2 + p) * 256 + c] = s;
    else         g_kwin[(n * P2 + p) * 256 + (c - 256)] = s;
}

// ---------------- routing logits + top-4 (set selection == lax.top_k set) ---
__global__ __launch_bounds__(256) void topk_kernel()
{
    int p = blockIdx.x, n = blockIdx.y;
    __shared__ float qs[256];
    __shared__ float lg[64];
    int tid = threadIdx.x;
    qs[tid] = g_qwin[(n * P2 + p) * 256 + tid];
    __syncthreads();
    if (tid < P2) {
        const float* kw = &g_kwin[(n * P2 + tid) * 256];
        float s = 0.0f;
#pragma unroll 8
        for (int cc = 0; cc < 256; cc++) s = fmaf(qs[cc], kw[cc], s);
        lg[tid] = s;
    }
    __syncthreads();
    if (tid == 0) {
        int sel[4];
        for (int t = 0; t < 4; t++) {
            float best = -1e30f; int bi = 0;
            for (int j = 0; j < P2; j++) {
                bool used = false;
                for (int u = 0; u < t; u++) if (sel[u] == j) used = true;
                float v = lg[j];
                if (!used && v > best) { best = v; bi = j; }
            }
            sel[t] = bi;
            g_ridx[(n * P2 + p) * 4 + t] = bi;
        }
    }
}

// ---------------- flash attention, fp16 HMMA: block per (n,p), warp = head --
// K smem: [64 keys][264 ch-padded]  (stride 264 halves -> conflict-free B frags)
// V smem: transposed [256 ch][72 key-padded]
#define KS_STRIDE 264
#define VT_STRIDE 72
#define ATTN_SMEM ((64 * KS_STRIDE + 256 * VT_STRIDE) * 2)
__global__ __launch_bounds__(256) void attn_kernel()
{
    extern __shared__ __align__(16) char dyn[];
    __half* ks = (__half*)dyn;
    __half* vt = (__half*)dyn + 64 * KS_STRIDE;
    __shared__ int selw[4];

    const int n = blockIdx.x / P2, p = blockIdx.x % P2;
    const int tid = threadIdx.x;
    const int m = tid >> 5;            // head
    const int l = tid & 31;
    const int gr = l >> 2, tc = (l & 3) << 1;

    if (tid < 4) selw[tid] = g_ridx[(n * P2 + p) * 4 + tid];

    // ---- Q fragments (64q x 32ch per head), pre-scaled by ASCALE ----
    uint32_t qa[4][2][4];
    const __half2 scl = __float2half2_rn(ASCALE);
#pragma unroll
    for (int mi = 0; mi < 4; mi++) {
        int r0 = (mi << 4) + gr;
        int t0 = win_token(n, p, r0);
        int t1 = win_token(n, p, r0 + 8);
#pragma unroll
        for (int kk = 0; kk < 2; kk++) {
            int ch = (m << 5) + (kk << 4) + tc;
            __half2 h0 = *(const __half2*)&g_qkvh[(size_t)t0 * QKVN + ch];
            __half2 h1 = *(const __half2*)&g_qkvh[(size_t)t1 * QKVN + ch];
            __half2 h2 = *(const __half2*)&g_qkvh[(size_t)t0 * QKVN + ch + 8];
            __half2 h3 = *(const __half2*)&g_qkvh[(size_t)t1 * QKVN + ch + 8];
            h0 = __hmul2(h0, scl); h1 = __hmul2(h1, scl);
            h2 = __hmul2(h2, scl); h3 = __hmul2(h3, scl);
            *(__half2*)&qa[mi][kk][0] = h0;
            *(__half2*)&qa[mi][kk][1] = h1;
            *(__half2*)&qa[mi][kk][2] = h2;
            *(__half2*)&qa[mi][kk][3] = h3;
        }
    }

    float oc[4][4][4];
#pragma unroll
    for (int a = 0; a < 4; a++)
#pragma unroll
        for (int b = 0; b < 4; b++)
#pragma unroll
            for (int c = 0; c < 4; c++) oc[a][b][c] = 0.0f;
    float mrow[4][2], lrow[4][2];
#pragma unroll
    for (int a = 0; a < 4; a++) {
        mrow[a][0] = mrow[a][1] = -1e30f;
        lrow[a][0] = lrow[a][1] = 0.0f;
    }

    for (int wl = 0; wl < 4; wl++) {
        __syncthreads();                       // selw ready / prev window done
        int sw = selw[wl];
        // ---- cooperative load: K [64][256] (coalesced, ch-fast) ----
#pragma unroll
        for (int i = 0; i < 8; i++) {
            int c = tid + (i << 8);            // 0..2047
            int row = c >> 5, ch8 = (c & 31) << 3;
            int t = win_token(n, sw, row);
            *(uint4*)&ks[row * KS_STRIDE + ch8] =
                *(const uint4*)&g_qkvh[(size_t)t * QKVN + 256 + ch8];
        }
        // ---- V transposed into vt[ch][key] (row-fast mapping) ----
#pragma unroll
        for (int i = 0; i < 8; i++) {
            int c = tid + (i << 8);
            int row = c & 63, ch8 = (c >> 6) << 3;
            int t = win_token(n, sw, row);
            uint4 v4 = *(const uint4*)&g_qkvh[(size_t)t * QKVN + 512 + ch8];
            __half2 h2[4];
            *(uint4*)h2 = v4;
#pragma unroll
            for (int j = 0; j < 4; j++) {
                vt[(ch8 + 2*j)     * VT_STRIDE + row] = h2[j].x;
                vt[(ch8 + 2*j + 1) * VT_STRIDE + row] = h2[j].y;
            }
        }
        __syncthreads();

        // ---- 4 subchunks of 16 keys, online softmax ----
#pragma unroll
        for (int t = 0; t < 4; t++) {
            int key0 = t << 4;
            uint32_t kb[2][2][2];
#pragma unroll
            for (int ni = 0; ni < 2; ni++)
#pragma unroll
                for (int kk = 0; kk < 2; kk++) {
                    int base = (key0 + (ni << 3) + gr) * KS_STRIDE
                             + (m << 5) + (kk << 4) + tc;
                    kb[ni][kk][0] = *(const uint32_t*)&ks[base];
                    kb[ni][kk][1] = *(const uint32_t*)&ks[base + 8];
                }
            uint32_t paf[4][4];
#pragma unroll
            for (int mi = 0; mi < 4; mi++) {
                float s4[2][4];
#pragma unroll
                for (int ni = 0; ni < 2; ni++)
#pragma unroll
                    for (int j = 0; j < 4; j++) s4[ni][j] = 0.0f;
#pragma unroll
                for (int kk = 0; kk < 2; kk++)
#pragma unroll
                    for (int ni = 0; ni < 2; ni++)
                        mma_f16(s4[ni], qa[mi][kk], kb[ni][kk]);
                // row maxima (h=0: regs 0,1; h=1: regs 2,3)
                float mx0 = fmaxf(fmaxf(s4[0][0], s4[0][1]), fmaxf(s4[1][0], s4[1][1]));
                float mx1 = fmaxf(fmaxf(s4[0][2], s4[0][3]), fmaxf(s4[1][2], s4[1][3]));
#pragma unroll
                for (int off = 1; off <= 2; off <<= 1) {
                    mx0 = fmaxf(mx0, __shfl_xor_sync(~0u, mx0, off));
                    mx1 = fmaxf(mx1, __shfl_xor_sync(~0u, mx1, off));
                }
                float mn0 = fmaxf(mrow[mi][0], mx0);
                float mn1 = fmaxf(mrow[mi][1], mx1);
                float cr0 = fexp(mrow[mi][0] - mn0);
                float cr1 = fexp(mrow[mi][1] - mn1);
                mrow[mi][0] = mn0; mrow[mi][1] = mn1;
                float e00 = fexp(s4[0][0] - mn0), e01 = fexp(s4[0][1] - mn0);
                float e02 = fexp(s4[0][2] - mn1), e03 = fexp(s4[0][3] - mn1);
                float e10 = fexp(s4[1][0] - mn0), e11 = fexp(s4[1][1] - mn0);
                float e12 = fexp(s4[1][2] - mn1), e13 = fexp(s4[1][3] - mn1);
                float sm0 = e00 + e01 + e10 + e11;
                float sm1 = e02 + e03 + e12 + e13;
#pragma unroll
                for (int off = 1; off <= 2; off <<= 1) {
                    sm0 += __shfl_xor_sync(~0u, sm0, off);
                    sm1 += __shfl_xor_sync(~0u, sm1, off);
                }
                lrow[mi][0] = lrow[mi][0] * cr0 + sm0;
                lrow[mi][1] = lrow[mi][1] * cr1 + sm1;
#pragma unroll
                for (int ni = 0; ni < 4; ni++) {
                    oc[mi][ni][0] *= cr0; oc[mi][ni][1] *= cr0;
                    oc[mi][ni][2] *= cr1; oc[mi][ni][3] *= cr1;
                }
                paf[mi][0] = pack_h2(e00, e01);
                paf[mi][1] = pack_h2(e02, e03);
                paf[mi][2] = pack_h2(e10, e11);
                paf[mi][3] = pack_h2(e12, e13);
            }
            uint32_t vb[4][2];
#pragma unroll
            for (int ni = 0; ni < 4; ni++) {
                int base = ((m << 5) + (ni << 3) + gr) * VT_STRIDE + key0 + tc;
                vb[ni][0] = *(const uint32_t*)&vt[base];
                vb[ni][1] = *(const uint32_t*)&vt[base + 8];
            }
#pragma unroll
            for (int mi = 0; mi < 4; mi++)
#pragma unroll
                for (int ni = 0; ni < 4; ni++)
                    mma_f16(oc[mi][ni], paf[mi], vb[ni]);
        }
    }

    // ---- write O (fp32, pre-lepe) ----
#pragma unroll
    for (int mi = 0; mi < 4; mi++) {
#pragma unroll
        for (int h = 0; h < 2; h++) {
            int row = (mi << 4) + gr + (h << 3);
            int tok = win_token(n, p, row);
            float inv = 1.0f / lrow[mi][h];
#pragma unroll
            for (int ni = 0; ni < 4; ni++) {
                float2 o2;
                o2.x = oc[mi][ni][h * 2 + 0] * inv;
                o2.y = oc[mi][ni][h * 2 + 1] * inv;
                *(float2*)&g_attn[(size_t)tok * 256 + (m << 5) + (ni << 3) + tc] = o2;
            }
        }
    }
}

// ---------------- depthwise 5x5 lepe + add + fp16 convert -------------------
__global__ __launch_bounds__(256) void lepe_kernel(
    const float* __restrict__ w, const float* __restrict__ b)
{
    int gid = blockIdx.x * 256 + threadIdx.x;   // TOK*64 c4-groups
    int t = gid >> 6;
    int c = (gid & 63) << 2;
    int n = t / 3136, rem = t % 3136, y = rem / 56, x = rem % 56;
    float4 bb = *(const float4*)(b + c);
    float av[4] = {bb.x, bb.y, bb.z, bb.w};
#pragma unroll
    for (int dy = 0; dy < 5; dy++) {
        int yy = y + dy - 2;
        if ((unsigned)yy >= 56u) continue;
#pragma unroll
        for (int dx = 0; dx < 5; dx++) {
            int xx = x + dx - 2;
            if ((unsigned)xx >= 56u) continue;
            float4 vv = *(const float4*)&g_qkv[(size_t)((n * 56 + yy) * 56 + xx) * QKVN + 512 + c];
            float4 ww = *(const float4*)(w + (dy * 5 + dx) * 256 + c);
            av[0] = fmaf(vv.x, ww.x, av[0]);
            av[1] = fmaf(vv.y, ww.y, av[1]);
            av[2] = fmaf(vv.z, ww.z, av[2]);
            av[3] = fmaf(vv.w, ww.w, av[3]);
        }
    }
    float4 cur = *(const float4*)&g_attn[(size_t)t * 256 + c];
    uint32_t pk[2];
    pk[0] = pack_h2(cur.x + av[0], cur.y + av[1]);
    pk[1] = pack_h2(cur.z + av[2], cur.w + av[3]);
    *(uint2*)&g_attnh[(size_t)t * 256 + c] = *(uint2*)pk;
}

// ---------------- launch ----------------------------------------------------
extern "C" void kernel_launch(void* const* d_in, const int* in_sizes, int n_in,
                              void* d_out, int out_size)
{
    const float* x     = (const float*)d_in[0];
    const float* ln1g  = (const float*)d_in[1];
    const float* ln1b  = (const float*)d_in[2];
    const float* qkvw  = (const float*)d_in[3];
    const float* qkvb  = (const float*)d_in[4];
    const float* lepew = (const float*)d_in[5];
    const float* lepeb = (const float*)d_in[6];
    const float* wow   = (const float*)d_in[7];
    const float* wob   = (const float*)d_in[8];
    const float* ln2g  = (const float*)d_in[9];
    const float* ln2b  = (const float*)d_in[10];
    const float* w1    = (const float*)d_in[11];
    const float* b1    = (const float*)d_in[12];
    const float* w2    = (const float*)d_in[13];
    const float* b2    = (const float*)d_in[14];

    __half *h1h, *qkvh, *attnh, *hidh, *wt;
    float *qkv, *attn, *y1;
    cudaGetSymbolAddress((void**)&h1h,   g_h1h);
    cudaGetSymbolAddress((void**)&qkv,   g_qkv);
    cudaGetSymbolAddress((void**)&qkvh,  g_qkvh);
    cudaGetSymbolAddress((void**)&attn,  g_attn);
    cudaGetSymbolAddress((void**)&attnh, g_attnh);
    cudaGetSymbolAddress((void**)&y1,    g_y1);
    cudaGetSymbolAddress((void**)&hidh,  g_hidh);
    cudaGetSymbolAddress((void**)&wt,    g_wt);

    cudaFuncSetAttribute(attn_kernel,
                         cudaFuncAttributeMaxDynamicSharedMemorySize, ATTN_SMEM);

    // weight transpose+convert (tiny)
    wtrans_kernel<<<768 * 256 / 256, 256>>>(qkvw, wt + WT_QKV, 256, 768);
    wtrans_kernel<<<256 * 256 / 256, 256>>>(wow,  wt + WT_WO,  256, 256);
    wtrans_kernel<<<1024 * 256 / 256, 256>>>(w1,  wt + WT_W1,  256, 1024);
    wtrans_kernel<<<256 * 1024 / 256, 256>>>(w2,  wt + WT_W2,  1024, 256);

    // 1. LN1 -> fp16
    ln_h_kernel<<<3136, 256>>>(x, ln1g, ln1b, h1h);
    // 2. qkv projection (fp32 + fp16 copy)
    gemm_mma_kernel<<<dim3(12, 196), 256>>>(h1h, wt + WT_QKV, qkvb, nullptr,
                                            qkv, qkvh, TOK, 768, 256, 0);
    // 3-4. routing (fp32 path)
    winmean_kernel<<<392, 512>>>();
    topk_kernel<<<dim3(49, 8), 256>>>();
    // 5. gathered window attention (fp16 HMMA flash)
    attn_kernel<<<392, 256, ATTN_SMEM>>>();
    // 6. lepe depthwise conv + add + fp16 convert
    lepe_kernel<<<6272, 256>>>(lepew, lepeb);
    // 7. output projection + residual with x
    gemm_mma_kernel<<<dim3(4, 196), 256>>>(attnh, wt + WT_WO, wob, x,
                                           y1, nullptr, TOK, 256, 256, 2);
    // 8. LN2 -> fp16
    ln_h_kernel<<<3136, 256>>>(y1, ln2g, ln2b, h1h);
    // 9. MLP up + exact GELU, fp16 out
    gemm_mma_kernel<<<dim3(16, 196), 256>>>(h1h, wt + WT_W1, b1, nullptr,
                                            nullptr, hidh, TOK, 1024, 256, 1);
    // 10. MLP down + residual -> d_out
    gemm_mma_kernel<<<dim3(4, 196), 256>>>(hidh, wt + WT_W2, b2, y1,
                                           (float*)d_out, nullptr, TOK, 256, 1024, 2);
}

// round 12
// speedup vs baseline: 3.3987x; 1.0520x over previous
#include <cuda_runtime.h>
#include <cuda_fp16.h>
#include <math.h>
#include <stdint.h>

#define TOK   25088      // 8*56*56
#define CDIM  256
#define QKVN  768
#define HIDN  1024
#define HW    56
#define P2    49
#define ASCALE 0.0625f   // 256^-0.5

// ---------------- scratch (device globals; no allocation allowed) ----------
__device__ __half g_h1h[TOK * CDIM];      // LN output (fp16, GEMM A)
__device__ __half g_qkvh[TOK * QKVN];     // qkv projections (fp16, sole copy)
__device__ __half g_attnh[TOK * CDIM];    // attn out, then +lepe in place (fp16)
__device__ float  g_y1[TOK * CDIM];       // residual stream after attn
__device__ __half g_hidh[TOK * HIDN];     // MLP hidden (fp16, from epi)
// transposed fp16 weights, concatenated: [N x K] layouts
#define WT_QKV 0
#define WT_WO  (768*256)
#define WT_W1  (WT_WO + 256*256)
#define WT_W2  (WT_W1 + 1024*256)
__device__ __half g_wt[768*256 + 256*256 + 1024*256 + 256*1024];
__device__ float g_qwin[8 * P2 * 256];
__device__ float g_kwin[8 * P2 * 256];
__device__ int   g_ridx[8 * P2 * 4];

// ---------------- small helpers ---------------------------------------------
__device__ __forceinline__ uint32_t smem_u32(const void* p) {
    uint32_t a;
    asm("{ .reg .u64 t; cvta.to.shared.u64 t, %1; cvt.u32.u64 %0, t; }"
        : "=r"(a) : "l"(p));
    return a;
}
#define CPA16(dst, src) \
    asm volatile("cp.async.cg.shared.global [%0], [%1], 16;" :: "r"(dst), "l"(src))
#define CPA_COMMIT() asm volatile("cp.async.commit_group;" ::: "memory")

__device__ __forceinline__ void mma_f16(float* c, const uint32_t* a, const uint32_t* b) {
    asm volatile(
        "mma.sync.aligned.m16n8k16.row.col.f32.f16.f16.f32 "
        "{%0,%1,%2,%3}, {%4,%5,%6,%7}, {%8,%9}, {%0,%1,%2,%3};"
        : "+f"(c[0]), "+f"(c[1]), "+f"(c[2]), "+f"(c[3])
        : "r"(a[0]), "r"(a[1]), "r"(a[2]), "r"(a[3]), "r"(b[0]), "r"(b[1]));
}

__device__ __forceinline__ uint32_t pack_h2(float v0, float v1) {
    __half2 pk = __floats2half2_rn(v0, v1);
    uint32_t r;
    *(__half2*)&r = pk;
    return r;
}

// ---------------- fp16 HMMA GEMM: 128x64 tile, BK=32, cp.async 2-stage ------
// A: [M,K] fp16 row-major.  Bt: [N,K] fp16 row-major (pre-transposed weight).
// epi: 0 = bias (fp16 out), 1 = bias+GELU (fp16 out), 2 = bias+res (fp32 out)
#define SROW 40   // smem row stride in halves (80B) -> conflict-free frag loads
__global__ __launch_bounds__(256) void gemm_mma_kernel(
    const __half* __restrict__ A, const __half* __restrict__ Bt,
    const float* __restrict__ bias, const float* __restrict__ res,
    float* __restrict__ Cf, __half* __restrict__ Ch,
    int M, int N, int K, int epi)
{
    __shared__ __align__(16) __half sa[2][128][SROW];
    __shared__ __align__(16) __half sb[2][64][SROW];

    const int tid = threadIdx.x;
    const int wid = tid >> 5, l = tid & 31;
    const int wm = wid >> 1, wn = wid & 1;            // warp grid 4x2
    const int m0 = blockIdx.y << 7, n0 = blockIdx.x << 6;
    const int gr = l >> 2, tc = (l & 3) << 1;

    const int lr = tid >> 2, lc = (tid & 3) << 3;
    const __half* Ap0 = A + (size_t)(m0 + lr) * K + lc;
    const __half* Ap1 = A + (size_t)(m0 + lr + 64) * K + lc;
    const __half* Bp  = Bt + (size_t)(n0 + lr) * K + lc;
    const uint32_t sa0 = smem_u32(&sa[0][lr][lc]);
    const uint32_t sa1 = smem_u32(&sa[0][lr + 64][lc]);
    const uint32_t sb0 = smem_u32(&sb[0][lr][lc]);
    const uint32_t ABUF = 128 * SROW * 2, BBUF = 64 * SROW * 2;

    float acc[2][4][4];
#pragma unroll
    for (int i = 0; i < 2; i++)
#pragma unroll
        for (int j = 0; j < 4; j++)
#pragma unroll
            for (int v = 0; v < 4; v++) acc[i][j][v] = 0.0f;

    const int nst = K >> 5;
    CPA16(sa0, Ap0); CPA16(sa1, Ap1); CPA16(sb0, Bp);
    CPA_COMMIT();

    int buf = 0;
    for (int s = 0; s < nst; s++) {
        if (s + 1 < nst) {
            int k0 = (s + 1) << 5;
            int ob = (buf ^ 1);
            CPA16(sa0 + ob * ABUF, Ap0 + k0);
            CPA16(sa1 + ob * ABUF, Ap1 + k0);
            CPA16(sb0 + ob * BBUF, Bp + k0);
            CPA_COMMIT();
            asm volatile("cp.async.wait_group 1;" ::: "memory");
        } else {
            asm volatile("cp.async.wait_group 0;" ::: "memory");
        }
        __syncthreads();

#pragma unroll
        for (int kk = 0; kk < 32; kk += 16) {
            uint32_t af[2][4], bfr[4][2];
#pragma unroll
            for (int mi = 0; mi < 2; mi++) {
                int r = (wm << 5) + (mi << 4) + gr;
                af[mi][0] = *(const uint32_t*)&sa[buf][r][kk + tc];
                af[mi][1] = *(const uint32_t*)&sa[buf][r + 8][kk + tc];
                af[mi][2] = *(const uint32_t*)&sa[buf][r][kk + tc + 8];
                af[mi][3] = *(const uint32_t*)&sa[buf][r + 8][kk + tc + 8];
            }
#pragma unroll
            for (int ni = 0; ni < 4; ni++) {
                int r = (wn << 5) + (ni << 3) + gr;
                bfr[ni][0] = *(const uint32_t*)&sb[buf][r][kk + tc];
                bfr[ni][1] = *(const uint32_t*)&sb[buf][r][kk + tc + 8];
            }
#pragma unroll
            for (int mi = 0; mi < 2; mi++)
#pragma unroll
                for (int ni = 0; ni < 4; ni++)
                    mma_f16(acc[mi][ni], af[mi], bfr[ni]);
        }
        __syncthreads();
        buf ^= 1;
    }

    // ---------------- epilogue ----------------
    float2 bv[4];
#pragma unroll
    for (int ni = 0; ni < 4; ni++)
        bv[ni] = *(const float2*)(bias + n0 + (wn << 5) + (ni << 3) + tc);

#pragma unroll
    for (int mi = 0; mi < 2; mi++) {
#pragma unroll
        for (int h = 0; h < 2; h++) {          // row halves (+0 / +8)
            int row = m0 + (wm << 5) + (mi << 4) + gr + (h << 3);
#pragma unroll
            for (int ni = 0; ni < 4; ni++) {
                int col = n0 + (wn << 5) + (ni << 3) + tc;
                float v0 = acc[mi][ni][h * 2 + 0] + bv[ni].x;
                float v1 = acc[mi][ni][h * 2 + 1] + bv[ni].y;
                if (epi == 2) {
                    float2 r2 = *(const float2*)(res + (size_t)row * N + col);
                    float2 o2;
                    o2.x = v0 + r2.x; o2.y = v1 + r2.y;
                    *(float2*)(Cf + (size_t)row * N + col) = o2;
                } else {
                    if (epi == 1) {
                        v0 = 0.5f * v0 * (1.0f + erff(v0 * 0.7071067811865476f));
                        v1 = 0.5f * v1 * (1.0f + erff(v1 * 0.7071067811865476f));
                    }
                    *(uint32_t*)(Ch + (size_t)row * N + col) = pack_h2(v0, v1);
                }
            }
        }
    }
}

// ---------------- helpers ---------------------------------------------------
__device__ __forceinline__ int win_token(int n, int p, int pix) {
    int wj = p / 7, wi = p % 7;
    int y = wj * 8 + (pix >> 3);
    int x = wi * 8 + (pix & 7);
    return (n * HW + y) * HW + x;
}

// exp(x) for x <= 0 on the FMA pipe (avoids MUFU throughput wall).
__device__ __forceinline__ float fexp(float x) {
    float z = fmaxf(x * 1.4426950408889634f, -120.0f);
    float t = z + 12582912.0f;                       // 1.5*2^23 magic
    int   ni = __float_as_int(t) - __float_as_int(12582912.0f);
    float f = z - (t - 12582912.0f);
    float p = fmaf(f, 0.0013333558f, 0.0096181291f);
    p = fmaf(f, p, 0.0555041087f);
    p = fmaf(f, p, 0.2402265070f);
    p = fmaf(f, p, 0.6931471806f);
    p = fmaf(f, p, 1.0f);
    return p * __int_as_float((ni + 127) << 23);
}

// ---------------- LayerNorm: one warp per token, fp16 output ----------------
__global__ __launch_bounds__(256) void ln_h_kernel(
    const float* __restrict__ x, const float* __restrict__ g,
    const float* __restrict__ b, __half* __restrict__ o)
{
    int w = blockIdx.x * 8 + (threadIdx.x >> 5);
    int lane = threadIdx.x & 31;
    const float* xp = x + (size_t)w * 256 + lane * 8;
    float4 a = *(const float4*)xp;
    float4 c = *(const float4*)(xp + 4);
    float s  = a.x + a.y + a.z + a.w + c.x + c.y + c.z + c.w;
    float ss = a.x*a.x + a.y*a.y + a.z*a.z + a.w*a.w
             + c.x*c.x + c.y*c.y + c.z*c.z + c.w*c.w;
#pragma unroll
    for (int off = 16; off; off >>= 1) {
        s  += __shfl_xor_sync(~0u, s,  off);
        ss += __shfl_xor_sync(~0u, ss, off);
    }
    float mu  = s * (1.0f / 256.0f);
    float var = ss * (1.0f / 256.0f) - mu * mu;
    float inv = rsqrtf(var + 1e-6f);
    float4 g1 = *(const float4*)(g + lane * 8);
    float4 g2 = *(const float4*)(g + lane * 8 + 4);
    float4 b1 = *(const float4*)(b + lane * 8);
    float4 b2 = *(const float4*)(b + lane * 8 + 4);
    float v[8];
    v[0] = (a.x - mu) * inv * g1.x + b1.x;
    v[1] = (a.y - mu) * inv * g1.y + b1.y;
    v[2] = (a.z - mu) * inv * g1.z + b1.z;
    v[3] = (a.w - mu) * inv * g1.w + b1.w;
    v[4] = (c.x - mu) * inv * g2.x + b2.x;
    v[5] = (c.y - mu) * inv * g2.y + b2.y;
    v[6] = (c.z - mu) * inv * g2.z + b2.z;
    v[7] = (c.w - mu) * inv * g2.w + b2.w;
    uint32_t pk[4];
#pragma unroll
    for (int j = 0; j < 4; j++) pk[j] = pack_h2(v[2*j], v[2*j+1]);
    *(uint4*)(o + (size_t)w * 256 + lane * 8) = *(uint4*)pk;
}

// ---------------- weight transpose+convert via smem tile --------------------
// w[K][N] fp32 -> o[N][K] fp16; K,N multiples of 32.
__global__ __launch_bounds__(256) void wtrans_kernel(
    const float* __restrict__ w, __half* __restrict__ o, int K, int N)
{
    __shared__ float tile[32][33];
    int kb = blockIdx.x << 5, nb = blockIdx.y << 5;
    int tx = threadIdx.x & 31, ty = threadIdx.x >> 5;   // 32 x 8
#pragma unroll
    for (int i = 0; i < 4; i++)
        tile[ty + (i << 3)][tx] = w[(size_t)(kb + ty + (i << 3)) * N + nb + tx];
    __syncthreads();
#pragma unroll
    for (int i = 0; i < 4; i++)
        o[(size_t)(nb + ty + (i << 3)) * K + kb + tx] =
            __float2half_rn(tile[tx][ty + (i << 3)]);
}

// ---------------- per-window q/k means (fp16 in, fp32 out) ------------------
__global__ __launch_bounds__(512) void winmean_kernel()
{
    int n = blockIdx.x / P2, p = blockIdx.x % P2;
    int c = threadIdx.x;   // 0..511: q channels 0..255, k channels 256..511
    float s = 0.0f;
#pragma unroll 4
    for (int pix = 0; pix < 64; pix++)
        s += __half2float(g_qkvh[(size_t)win_token(n, p, pix) * QKVN + c]);
    s *= (1.0f / 64.0f);
    if (c < 256) g_qwin[(n * P2 + p) * 256 + c] = s;
    else         g_kwin[(n * P2 + p) * 256 + (c - 256)] = s;
}

// ---------------- routing logits + top-4 (set selection == lax.top_k set) ---
// 4 lanes per logit, warp-uniform execution (clamped index; guarded write).
__global__ __launch_bounds__(256) void topk_kernel()
{
    int p = blockIdx.x, n = blockIdx.y;
    __shared__ float qs[256];
    __shared__ float lg[64];
    int tid = threadIdx.x;
    qs[tid] = g_qwin[(n * P2 + p) * 256 + tid];
    __syncthreads();
    int j = tid >> 2, part = tid & 3;
    int jc = j < P2 ? j : P2 - 1;            // clamp: keep all lanes convergent
    {
        const float* kw = &g_kwin[(n * P2 + jc) * 256 + (part << 6)];
        const float* qq = &qs[part << 6];
        float s = 0.0f;
#pragma unroll 16
        for (int cc = 0; cc < 64; cc++) s = fmaf(qq[cc], kw[cc], s);
        s += __shfl_xor_sync(~0u, s, 1);
        s += __shfl_xor_sync(~0u, s, 2);
        if (part == 0 && j < P2) lg[j] = s;
    }
    __syncthreads();
    if (tid == 0) {
        int sel[4];
        for (int t = 0; t < 4; t++) {
            float best = -1e30f; int bi = 0;
            for (int jj = 0; jj < P2; jj++) {
                bool used = false;
                for (int u = 0; u < t; u++) if (sel[u] == jj) used = true;
                float v = lg[jj];
                if (!used && v > best) { best = v; bi = jj; }
            }
            sel[t] = bi;
            g_ridx[(n * P2 + p) * 4 + t] = bi;
        }
    }
}

// ---------------- flash attention, fp16 HMMA: block per (n,p), warp = head --
// K smem: [64 keys][264 ch-padded]  (stride 264 halves -> conflict-free B frags)
// V smem: transposed [256 ch][72 key-padded]
#define KS_STRIDE 264
#define VT_STRIDE 72
#define ATTN_SMEM ((64 * KS_STRIDE + 256 * VT_STRIDE) * 2)
__global__ __launch_bounds__(256) void attn_kernel()
{
    extern __shared__ __align__(16) char dyn[];
    __half* ks = (__half*)dyn;
    __half* vt = (__half*)dyn + 64 * KS_STRIDE;
    __shared__ int selw[4];

    const int n = blockIdx.x / P2, p = blockIdx.x % P2;
    const int tid = threadIdx.x;
    const int m = tid >> 5;            // head
    const int l = tid & 31;
    const int gr = l >> 2, tc = (l & 3) << 1;

    if (tid < 4) selw[tid] = g_ridx[(n * P2 + p) * 4 + tid];

    // ---- Q fragments (64q x 32ch per head), pre-scaled by ASCALE ----
    uint32_t qa[4][2][4];
    const __half2 scl = __float2half2_rn(ASCALE);
#pragma unroll
    for (int mi = 0; mi < 4; mi++) {
        int r0 = (mi << 4) + gr;
        int t0 = win_token(n, p, r0);
        int t1 = win_token(n, p, r0 + 8);
#pragma unroll
        for (int kk = 0; kk < 2; kk++) {
            int ch = (m << 5) + (kk << 4) + tc;
            __half2 h0 = *(const __half2*)&g_qkvh[(size_t)t0 * QKVN + ch];
            __half2 h1 = *(const __half2*)&g_qkvh[(size_t)t1 * QKVN + ch];
            __half2 h2 = *(const __half2*)&g_qkvh[(size_t)t0 * QKVN + ch + 8];
            __half2 h3 = *(const __half2*)&g_qkvh[(size_t)t1 * QKVN + ch + 8];
            h0 = __hmul2(h0, scl); h1 = __hmul2(h1, scl);
            h2 = __hmul2(h2, scl); h3 = __hmul2(h3, scl);
            *(__half2*)&qa[mi][kk][0] = h0;
            *(__half2*)&qa[mi][kk][1] = h1;
            *(__half2*)&qa[mi][kk][2] = h2;
            *(__half2*)&qa[mi][kk][3] = h3;
        }
    }

    float oc[4][4][4];
#pragma unroll
    for (int a = 0; a < 4; a++)
#pragma unroll
        for (int b = 0; b < 4; b++)
#pragma unroll
            for (int c = 0; c < 4; c++) oc[a][b][c] = 0.0f;
    float mrow[4][2], lrow[4][2];
#pragma unroll
    for (int a = 0; a < 4; a++) {
        mrow[a][0] = mrow[a][1] = -1e30f;
        lrow[a][0] = lrow[a][1] = 0.0f;
    }

    for (int wl = 0; wl < 4; wl++) {
        __syncthreads();                       // selw ready / prev window done
        int sw = selw[wl];
        // ---- cooperative load: K [64][256] (coalesced, ch-fast) ----
#pragma unroll
        for (int i = 0; i < 8; i++) {
            int c = tid + (i << 8);            // 0..2047
            int row = c >> 5, ch8 = (c & 31) << 3;
            int t = win_token(n, sw, row);
            *(uint4*)&ks[row * KS_STRIDE + ch8] =
                *(const uint4*)&g_qkvh[(size_t)t * QKVN + 256 + ch8];
        }
        // ---- V transposed into vt[ch][key] (row-fast mapping) ----
#pragma unroll
        for (int i = 0; i < 8; i++) {
            int c = tid + (i << 8);
            int row = c & 63, ch8 = (c >> 6) << 3;
            int t = win_token(n, sw, row);
            uint4 v4 = *(const uint4*)&g_qkvh[(size_t)t * QKVN + 512 + ch8];
            __half2 h2[4];
            *(uint4*)h2 = v4;
#pragma unroll
            for (int j = 0; j < 4; j++) {
                vt[(ch8 + 2*j)     * VT_STRIDE + row] = h2[j].x;
                vt[(ch8 + 2*j + 1) * VT_STRIDE + row] = h2[j].y;
            }
        }
        __syncthreads();

        // ---- 4 subchunks of 16 keys, online softmax ----
#pragma unroll
        for (int t = 0; t < 4; t++) {
            int key0 = t << 4;
            uint32_t kb[2][2][2];
#pragma unroll
            for (int ni = 0; ni < 2; ni++)
#pragma unroll
                for (int kk = 0; kk < 2; kk++) {
                    int base = (key0 + (ni << 3) + gr) * KS_STRIDE
                             + (m << 5) + (kk << 4) + tc;
                    kb[ni][kk][0] = *(const uint32_t*)&ks[base];
                    kb[ni][kk][1] = *(const uint32_t*)&ks[base + 8];
                }
            uint32_t paf[4][4];
#pragma unroll
            for (int mi = 0; mi < 4; mi++) {
                float s4[2][4];
#pragma unroll
                for (int ni = 0; ni < 2; ni++)
#pragma unroll
                    for (int j = 0; j < 4; j++) s4[ni][j] = 0.0f;
#pragma unroll
                for (int kk = 0; kk < 2; kk++)
#pragma unroll
                    for (int ni = 0; ni < 2; ni++)
                        mma_f16(s4[ni], qa[mi][kk], kb[ni][kk]);
                float mx0 = fmaxf(fmaxf(s4[0][0], s4[0][1]), fmaxf(s4[1][0], s4[1][1]));
                float mx1 = fmaxf(fmaxf(s4[0][2], s4[0][3]), fmaxf(s4[1][2], s4[1][3]));
#pragma unroll
                for (int off = 1; off <= 2; off <<= 1) {
                    mx0 = fmaxf(mx0, __shfl_xor_sync(~0u, mx0, off));
                    mx1 = fmaxf(mx1, __shfl_xor_sync(~0u, mx1, off));
                }
                float mn0 = fmaxf(mrow[mi][0], mx0);
                float mn1 = fmaxf(mrow[mi][1], mx1);
                float cr0 = fexp(mrow[mi][0] - mn0);
                float cr1 = fexp(mrow[mi][1] - mn1);
                mrow[mi][0] = mn0; mrow[mi][1] = mn1;
                float e00 = fexp(s4[0][0] - mn0), e01 = fexp(s4[0][1] - mn0);
                float e02 = fexp(s4[0][2] - mn1), e03 = fexp(s4[0][3] - mn1);
                float e10 = fexp(s4[1][0] - mn0), e11 = fexp(s4[1][1] - mn0);
                float e12 = fexp(s4[1][2] - mn1), e13 = fexp(s4[1][3] - mn1);
                float sm0 = e00 + e01 + e10 + e11;
                float sm1 = e02 + e03 + e12 + e13;
#pragma unroll
                for (int off = 1; off <= 2; off <<= 1) {
                    sm0 += __shfl_xor_sync(~0u, sm0, off);
                    sm1 += __shfl_xor_sync(~0u, sm1, off);
                }
                lrow[mi][0] = lrow[mi][0] * cr0 + sm0;
                lrow[mi][1] = lrow[mi][1] * cr1 + sm1;
#pragma unroll
                for (int ni = 0; ni < 4; ni++) {
                    oc[mi][ni][0] *= cr0; oc[mi][ni][1] *= cr0;
                    oc[mi][ni][2] *= cr1; oc[mi][ni][3] *= cr1;
                }
                paf[mi][0] = pack_h2(e00, e01);
                paf[mi][1] = pack_h2(e02, e03);
                paf[mi][2] = pack_h2(e10, e11);
                paf[mi][3] = pack_h2(e12, e13);
            }
            uint32_t vb[4][2];
#pragma unroll
            for (int ni = 0; ni < 4; ni++) {
                int base = ((m << 5) + (ni << 3) + gr) * VT_STRIDE + key0 + tc;
                vb[ni][0] = *(const uint32_t*)&vt[base];
                vb[ni][1] = *(const uint32_t*)&vt[base + 8];
            }
#pragma unroll
            for (int mi = 0; mi < 4; mi++)
#pragma unroll
                for (int ni = 0; ni < 4; ni++)
                    mma_f16(oc[mi][ni], paf[mi], vb[ni]);
        }
    }

    // ---- write O (fp16, pre-lepe) ----
#pragma unroll
    for (int mi = 0; mi < 4; mi++) {
#pragma unroll
        for (int h = 0; h < 2; h++) {
            int row = (mi << 4) + gr + (h << 3);
            int tok = win_token(n, p, row);
            float inv = 1.0f / lrow[mi][h];
#pragma unroll
            for (int ni = 0; ni < 4; ni++) {
                uint32_t pk = pack_h2(oc[mi][ni][h * 2 + 0] * inv,
                                      oc[mi][ni][h * 2 + 1] * inv);
                *(uint32_t*)&g_attnh[(size_t)tok * 256 + (m << 5) + (ni << 3) + tc] = pk;
            }
        }
    }
}

// ---------------- depthwise 5x5 lepe (fp16 v) + add in place ---------------
__global__ __launch_bounds__(256) void lepe_kernel(
    const float* __restrict__ w, const float* __restrict__ b)
{
    int gid = blockIdx.x * 256 + threadIdx.x;   // TOK*64 c4-groups
    int t = gid >> 6;
    int c = (gid & 63) << 2;
    int n = t / 3136, rem = t % 3136, y = rem / 56, x = rem % 56;
    float4 bb = *(const float4*)(b + c);
    float av[4] = {bb.x, bb.y, bb.z, bb.w};
#pragma unroll
    for (int dy = 0; dy < 5; dy++) {
        int yy = y + dy - 2;
        if ((unsigned)yy >= 56u) continue;
#pragma unroll
        for (int dx = 0; dx < 5; dx++) {
            int xx = x + dx - 2;
            if ((unsigned)xx >= 56u) continue;
            uint2 vv2 = *(const uint2*)&g_qkvh[(size_t)((n * 56 + yy) * 56 + xx) * QKVN + 512 + c];
            __half2 vh[2];
            *(uint2*)vh = vv2;
            float4 ww = *(const float4*)(w + (dy * 5 + dx) * 256 + c);
            av[0] = fmaf(__half2float(vh[0].x), ww.x, av[0]);
            av[1] = fmaf(__half2float(vh[0].y), ww.y, av[1]);
            av[2] = fmaf(__half2float(vh[1].x), ww.z, av[2]);
            av[3] = fmaf(__half2float(vh[1].y), ww.w, av[3]);
        }
    }
    uint2 cur2 = *(const uint2*)&g_attnh[(size_t)t * 256 + c];
    __half2 ch[2];
    *(uint2*)ch = cur2;
    uint32_t pk[2];
    pk[0] = pack_h2(__half2float(ch[0].x) + av[0], __half2float(ch[0].y) + av[1]);
    pk[1] = pack_h2(__half2float(ch[1].x) + av[2], __half2float(ch[1].y) + av[3]);
    *(uint2*)&g_attnh[(size_t)t * 256 + c] = *(uint2*)pk;
}

// ---------------- launch ----------------------------------------------------
extern "C" void kernel_launch(void* const* d_in, const int* in_sizes, int n_in,
                              void* d_out, int out_size)
{
    const float* x     = (const float*)d_in[0];
    const float* ln1g  = (const float*)d_in[1];
    const float* ln1b  = (const float*)d_in[2];
    const float* qkvw  = (const float*)d_in[3];
    const float* qkvb  = (const float*)d_in[4];
    const float* lepew = (const float*)d_in[5];
    const float* lepeb = (const float*)d_in[6];
    const float* wow   = (const float*)d_in[7];
    const float* wob   = (const float*)d_in[8];
    const float* ln2g  = (const float*)d_in[9];
    const float* ln2b  = (const float*)d_in[10];
    const float* w1    = (const float*)d_in[11];
    const float* b1    = (const float*)d_in[12];
    const float* w2    = (const float*)d_in[13];
    const float* b2    = (const float*)d_in[14];

    __half *h1h, *qkvh, *attnh, *hidh, *wt;
    float *y1;
    cudaGetSymbolAddress((void**)&h1h,   g_h1h);
    cudaGetSymbolAddress((void**)&qkvh,  g_qkvh);
    cudaGetSymbolAddress((void**)&attnh, g_attnh);
    cudaGetSymbolAddress((void**)&y1,    g_y1);
    cudaGetSymbolAddress((void**)&hidh,  g_hidh);
    cudaGetSymbolAddress((void**)&wt,    g_wt);

    cudaFuncSetAttribute(attn_kernel,
                         cudaFuncAttributeMaxDynamicSharedMemorySize, ATTN_SMEM);

    // weight transpose+convert (smem tile transpose)
    wtrans_kernel<<<dim3(256/32, 768/32),  dim3(256)>>>(qkvw, wt + WT_QKV, 256, 768);
    wtrans_kernel<<<dim3(256/32, 256/32),  dim3(256)>>>(wow,  wt + WT_WO,  256, 256);
    wtrans_kernel<<<dim3(256/32, 1024/32), dim3(256)>>>(w1,   wt + WT_W1,  256, 1024);
    wtrans_kernel<<<dim3(1024/32, 256/32), dim3(256)>>>(w2,   wt + WT_W2,  1024, 256);

    // 1. LN1 -> fp16
    ln_h_kernel<<<3136, 256>>>(x, ln1g, ln1b, h1h);
    // 2. qkv projection (fp16 out only)
    gemm_mma_kernel<<<dim3(12, 196), 256>>>(h1h, wt + WT_QKV, qkvb, nullptr,
                                            nullptr, qkvh, TOK, 768, 256, 0);
    // 3-4. routing (fp16 reads, fp32 accum)
    winmean_kernel<<<392, 512>>>();
    topk_kernel<<<dim3(49, 8), 256>>>();
    // 5. gathered window attention (fp16 HMMA flash) -> fp16
    attn_kernel<<<392, 256, ATTN_SMEM>>>();
    // 6. lepe depthwise conv + add in place (fp16)
    lepe_kernel<<<6272, 256>>>(lepew, lepeb);
    // 7. output projection + residual with x -> fp32 y1
    gemm_mma_kernel<<<dim3(4, 196), 256>>>(attnh, wt + WT_WO, wob, x,
                                           y1, nullptr, TOK, 256, 256, 2);
    // 8. LN2 -> fp16
    ln_h_kernel<<<3136, 256>>>(y1, ln2g, ln2b, h1h);
    // 9. MLP up + exact GELU, fp16 out
    gemm_mma_kernel<<<dim3(16, 196), 256>>>(h1h, wt + WT_W1, b1, nullptr,
                                            nullptr, hidh, TOK, 1024, 256, 1);
    // 10. MLP down + residual -> d_out
    gemm_mma_kernel<<<dim3(4, 196), 256>>>(hidh, wt + WT_W2, b2, y1,
                                           (float*)d_out, nullptr, TOK, 256, 1024, 2);
}

// round 13
// speedup vs baseline: 3.6161x; 1.0639x over previous
#include <cuda_runtime.h>
#include <cuda_fp16.h>
#include <math.h>
#include <stdint.h>

#define TOK   25088      // 8*56*56
#define CDIM  256
#define QKVN  768
#define HIDN  1024
#define HW    56
#define P2    49
#define ASCALE 0.0625f   // 256^-0.5

// ---------------- scratch (device globals; no allocation allowed) ----------
__device__ __half g_h1h[TOK * CDIM];      // LN output (fp16, GEMM A)
__device__ __half g_qkvh[TOK * QKVN];     // qkv projections (fp16, sole copy)
__device__ __half g_attnh[TOK * CDIM];    // attn out, then +lepe in place (fp16)
__device__ float  g_y1[TOK * CDIM];       // residual stream after attn
__device__ __half g_hidh[TOK * HIDN];     // MLP hidden (fp16, from epi)
// transposed fp16 weights, concatenated: [N x K] layouts
#define WT_QKV 0
#define WT_WO  (768*256)
#define WT_W1  (WT_WO + 256*256)
#define WT_W2  (WT_W1 + 1024*256)
__device__ __half g_wt[768*256 + 256*256 + 1024*256 + 256*1024];
__device__ float g_qwin[8 * P2 * 256];
__device__ float g_kwin[8 * P2 * 256];
__device__ int   g_ridx[8 * P2 * 4];

// ---------------- small helpers ---------------------------------------------
__device__ __forceinline__ uint32_t smem_u32(const void* p) {
    uint32_t a;
    asm("{ .reg .u64 t; cvta.to.shared.u64 t, %1; cvt.u32.u64 %0, t; }"
        : "=r"(a) : "l"(p));
    return a;
}
#define CPA16(dst, src) \
    asm volatile("cp.async.cg.shared.global [%0], [%1], 16;" :: "r"(dst), "l"(src))
#define CPA_COMMIT() asm volatile("cp.async.commit_group;" ::: "memory")

__device__ __forceinline__ void mma_f16(float* c, const uint32_t* a, const uint32_t* b) {
    asm volatile(
        "mma.sync.aligned.m16n8k16.row.col.f32.f16.f16.f32 "
        "{%0,%1,%2,%3}, {%4,%5,%6,%7}, {%8,%9}, {%0,%1,%2,%3};"
        : "+f"(c[0]), "+f"(c[1]), "+f"(c[2]), "+f"(c[3])
        : "r"(a[0]), "r"(a[1]), "r"(a[2]), "r"(a[3]), "r"(b[0]), "r"(b[1]));
}

__device__ __forceinline__ void ldsm_x2_trans(uint32_t& r0, uint32_t& r1, uint32_t addr) {
    asm volatile("ldmatrix.sync.aligned.m8n8.x2.trans.shared.b16 {%0,%1}, [%2];"
        : "=r"(r0), "=r"(r1) : "r"(addr));
}

__device__ __forceinline__ uint32_t pack_h2(float v0, float v1) {
    __half2 pk = __floats2half2_rn(v0, v1);
    uint32_t r;
    *(__half2*)&r = pk;
    return r;
}

// ---------------- fp16 HMMA GEMM: 128x128 tile, BK=32, cp.async 2-stage -----
// warp grid 2x4 (warp tile 64x32).  A: [M,K] fp16.  Bt: [N,K] fp16.
// epi: 0 = bias (fp16 out), 1 = bias+GELU (fp16 out), 2 = bias+res (fp32 out)
#define SROW 40   // smem row stride in halves (80B) -> conflict-free frag loads
__global__ __launch_bounds__(256) void gemm_mma_kernel(
    const __half* __restrict__ A, const __half* __restrict__ Bt,
    const float* __restrict__ bias, const float* __restrict__ res,
    float* __restrict__ Cf, __half* __restrict__ Ch,
    int M, int N, int K, int epi)
{
    __shared__ __align__(16) __half sa[2][128][SROW];
    __shared__ __align__(16) __half sb[2][128][SROW];

    const int tid = threadIdx.x;
    const int wid = tid >> 5, l = tid & 31;
    const int wm = wid >> 2, wn = wid & 3;            // warp grid 2x4
    const int m0 = blockIdx.y << 7, n0 = blockIdx.x << 7;
    const int gr = l >> 2, tc = (l & 3) << 1;

    const int lr = tid >> 2, lc = (tid & 3) << 3;     // 64 rows x 4x8 halves
    const __half* Ap0 = A + (size_t)(m0 + lr) * K + lc;
    const __half* Ap1 = A + (size_t)(m0 + lr + 64) * K + lc;
    const __half* Bp0 = Bt + (size_t)(n0 + lr) * K + lc;
    const __half* Bp1 = Bt + (size_t)(n0 + lr + 64) * K + lc;
    const uint32_t sa0 = smem_u32(&sa[0][lr][lc]);
    const uint32_t sa1 = smem_u32(&sa[0][lr + 64][lc]);
    const uint32_t sb0 = smem_u32(&sb[0][lr][lc]);
    const uint32_t sb1 = smem_u32(&sb[0][lr + 64][lc]);
    const uint32_t BUF = 128 * SROW * 2;

    float acc[4][4][4];
#pragma unroll
    for (int i = 0; i < 4; i++)
#pragma unroll
        for (int j = 0; j < 4; j++)
#pragma unroll
            for (int v = 0; v < 4; v++) acc[i][j][v] = 0.0f;

    const int nst = K >> 5;
    CPA16(sa0, Ap0); CPA16(sa1, Ap1); CPA16(sb0, Bp0); CPA16(sb1, Bp1);
    CPA_COMMIT();

    int buf = 0;
    for (int s = 0; s < nst; s++) {
        if (s + 1 < nst) {
            int k0 = (s + 1) << 5;
            int ob = (buf ^ 1);
            CPA16(sa0 + ob * BUF, Ap0 + k0);
            CPA16(sa1 + ob * BUF, Ap1 + k0);
            CPA16(sb0 + ob * BUF, Bp0 + k0);
            CPA16(sb1 + ob * BUF, Bp1 + k0);
            CPA_COMMIT();
            asm volatile("cp.async.wait_group 1;" ::: "memory");
        } else {
            asm volatile("cp.async.wait_group 0;" ::: "memory");
        }
        __syncthreads();

#pragma unroll
        for (int kk = 0; kk < 32; kk += 16) {
            uint32_t af[4][4], bfr[4][2];
#pragma unroll
            for (int mi = 0; mi < 4; mi++) {
                int r = (wm << 6) + (mi << 4) + gr;
                af[mi][0] = *(const uint32_t*)&sa[buf][r][kk + tc];
                af[mi][1] = *(const uint32_t*)&sa[buf][r + 8][kk + tc];
                af[mi][2] = *(const uint32_t*)&sa[buf][r][kk + tc + 8];
                af[mi][3] = *(const uint32_t*)&sa[buf][r + 8][kk + tc + 8];
            }
#pragma unroll
            for (int ni = 0; ni < 4; ni++) {
                int r = (wn << 5) + (ni << 3) + gr;
                bfr[ni][0] = *(const uint32_t*)&sb[buf][r][kk + tc];
                bfr[ni][1] = *(const uint32_t*)&sb[buf][r][kk + tc + 8];
            }
#pragma unroll
            for (int mi = 0; mi < 4; mi++)
#pragma unroll
                for (int ni = 0; ni < 4; ni++)
                    mma_f16(acc[mi][ni], af[mi], bfr[ni]);
        }
        __syncthreads();
        buf ^= 1;
    }

    // ---------------- epilogue ----------------
    float2 bv[4];
#pragma unroll
    for (int ni = 0; ni < 4; ni++)
        bv[ni] = *(const float2*)(bias + n0 + (wn << 5) + (ni << 3) + tc);

#pragma unroll
    for (int mi = 0; mi < 4; mi++) {
#pragma unroll
        for (int h = 0; h < 2; h++) {          // row halves (+0 / +8)
            int row = m0 + (wm << 6) + (mi << 4) + gr + (h << 3);
#pragma unroll
            for (int ni = 0; ni < 4; ni++) {
                int col = n0 + (wn << 5) + (ni << 3) + tc;
                float v0 = acc[mi][ni][h * 2 + 0] + bv[ni].x;
                float v1 = acc[mi][ni][h * 2 + 1] + bv[ni].y;
                if (epi == 2) {
                    float2 r2 = *(const float2*)(res + (size_t)row * N + col);
                    float2 o2;
                    o2.x = v0 + r2.x; o2.y = v1 + r2.y;
                    *(float2*)(Cf + (size_t)row * N + col) = o2;
                } else {
                    if (epi == 1) {
                        v0 = 0.5f * v0 * (1.0f + erff(v0 * 0.7071067811865476f));
                        v1 = 0.5f * v1 * (1.0f + erff(v1 * 0.7071067811865476f));
                    }
                    *(uint32_t*)(Ch + (size_t)row * N + col) = pack_h2(v0, v1);
                }
            }
        }
    }
}

// ---------------- helpers ---------------------------------------------------
__device__ __forceinline__ int win_token(int n, int p, int pix) {
    int wj = p / 7, wi = p % 7;
    int y = wj * 8 + (pix >> 3);
    int x = wi * 8 + (pix & 7);
    return (n * HW + y) * HW + x;
}

// exp(x) for x <= 0 on the FMA pipe (avoids MUFU throughput wall).
__device__ __forceinline__ float fexp(float x) {
    float z = fmaxf(x * 1.4426950408889634f, -120.0f);
    float t = z + 12582912.0f;                       // 1.5*2^23 magic
    int   ni = __float_as_int(t) - __float_as_int(12582912.0f);
    float f = z - (t - 12582912.0f);
    float p = fmaf(f, 0.0013333558f, 0.0096181291f);
    p = fmaf(f, p, 0.0555041087f);
    p = fmaf(f, p, 0.2402265070f);
    p = fmaf(f, p, 0.6931471806f);
    p = fmaf(f, p, 1.0f);
    return p * __int_as_float((ni + 127) << 23);
}

// ---------------- LayerNorm: one warp per token, fp16 output ----------------
__global__ __launch_bounds__(256) void ln_h_kernel(
    const float* __restrict__ x, const float* __restrict__ g,
    const float* __restrict__ b, __half* __restrict__ o)
{
    int w = blockIdx.x * 8 + (threadIdx.x >> 5);
    int lane = threadIdx.x & 31;
    const float* xp = x + (size_t)w * 256 + lane * 8;
    float4 a = *(const float4*)xp;
    float4 c = *(const float4*)(xp + 4);
    float s  = a.x + a.y + a.z + a.w + c.x + c.y + c.z + c.w;
    float ss = a.x*a.x + a.y*a.y + a.z*a.z + a.w*a.w
             + c.x*c.x + c.y*c.y + c.z*c.z + c.w*c.w;
#pragma unroll
    for (int off = 16; off; off >>= 1) {
        s  += __shfl_xor_sync(~0u, s,  off);
        ss += __shfl_xor_sync(~0u, ss, off);
    }
    float mu  = s * (1.0f / 256.0f);
    float var = ss * (1.0f / 256.0f) - mu * mu;
    float inv = rsqrtf(var + 1e-6f);
    float4 g1 = *(const float4*)(g + lane * 8);
    float4 g2 = *(const float4*)(g + lane * 8 + 4);
    float4 b1 = *(const float4*)(b + lane * 8);
    float4 b2 = *(const float4*)(b + lane * 8 + 4);
    float v[8];
    v[0] = (a.x - mu) * inv * g1.x + b1.x;
    v[1] = (a.y - mu) * inv * g1.y + b1.y;
    v[2] = (a.z - mu) * inv * g1.z + b1.z;
    v[3] = (a.w - mu) * inv * g1.w + b1.w;
    v[4] = (c.x - mu) * inv * g2.x + b2.x;
    v[5] = (c.y - mu) * inv * g2.y + b2.y;
    v[6] = (c.z - mu) * inv * g2.z + b2.z;
    v[7] = (c.w - mu) * inv * g2.w + b2.w;
    uint32_t pk[4];
#pragma unroll
    for (int j = 0; j < 4; j++) pk[j] = pack_h2(v[2*j], v[2*j+1]);
    *(uint4*)(o + (size_t)w * 256 + lane * 8) = *(uint4*)pk;
}

// ---------------- weight transpose+convert via smem tile --------------------
__global__ __launch_bounds__(256) void wtrans_kernel(
    const float* __restrict__ w, __half* __restrict__ o, int K, int N)
{
    __shared__ float tile[32][33];
    int kb = blockIdx.x << 5, nb = blockIdx.y << 5;
    int tx = threadIdx.x & 31, ty = threadIdx.x >> 5;   // 32 x 8
#pragma unroll
    for (int i = 0; i < 4; i++)
        tile[ty + (i << 3)][tx] = w[(size_t)(kb + ty + (i << 3)) * N + nb + tx];
    __syncthreads();
#pragma unroll
    for (int i = 0; i < 4; i++)
        o[(size_t)(nb + ty + (i << 3)) * K + kb + tx] =
            __float2half_rn(tile[tx][ty + (i << 3)]);
}

// ---------------- per-window q/k means (fp16 in, fp32 out) ------------------
__global__ __launch_bounds__(512) void winmean_kernel()
{
    int n = blockIdx.x / P2, p = blockIdx.x % P2;
    int c = threadIdx.x;   // 0..511: q channels 0..255, k channels 256..511
    float s = 0.0f;
#pragma unroll 4
    for (int pix = 0; pix < 64; pix++)
        s += __half2float(g_qkvh[(size_t)win_token(n, p, pix) * QKVN + c]);
    s *= (1.0f / 64.0f);
    if (c < 256) g_qwin[(n * P2 + p) * 256 + c] = s;
    else         g_kwin[(n * P2 + p) * 256 + (c - 256)] = s;
}

// ---------------- routing logits + top-4 (warp-uniform shfl) ----------------
__global__ __launch_bounds__(256) void topk_kernel()
{
    int p = blockIdx.x, n = blockIdx.y;
    __shared__ float qs[256];
    __shared__ float lg[64];
    int tid = threadIdx.x;
    qs[tid] = g_qwin[(n * P2 + p) * 256 + tid];
    __syncthreads();
    int j = tid >> 2, part = tid & 3;
    int jc = j < P2 ? j : P2 - 1;            // clamp: keep all lanes convergent
    {
        const float* kw = &g_kwin[(n * P2 + jc) * 256 + (part << 6)];
        const float* qq = &qs[part << 6];
        float s = 0.0f;
#pragma unroll 16
        for (int cc = 0; cc < 64; cc++) s = fmaf(qq[cc], kw[cc], s);
        s += __shfl_xor_sync(~0u, s, 1);
        s += __shfl_xor_sync(~0u, s, 2);
        if (part == 0 && j < P2) lg[j] = s;
    }
    __syncthreads();
    if (tid == 0) {
        int sel[4];
        for (int t = 0; t < 4; t++) {
            float best = -1e30f; int bi = 0;
            for (int jj = 0; jj < P2; jj++) {
                bool used = false;
                for (int u = 0; u < t; u++) if (sel[u] == jj) used = true;
                float v = lg[jj];
                if (!used && v > best) { best = v; bi = jj; }
            }
            sel[t] = bi;
            g_ridx[(n * P2 + p) * 4 + t] = bi;
        }
    }
}

// ---------------- flash attention, fp16 HMMA: block per (n,p), warp = head --
// KV smem: [64 keys][520 ch-padded]: cols 0..255 = K, 256..511 = V (row-major).
// V B-fragments via ldmatrix.x2.trans (no explicit transpose pass).
#define KV_STRIDE 520
#define ATTN_SMEM (64 * KV_STRIDE * 2)
__global__ __launch_bounds__(256) void attn_kernel()
{
    extern __shared__ __align__(16) char dyn[];
    __half* kv = (__half*)dyn;
    __shared__ int selw[4];

    const int n = blockIdx.x / P2, p = blockIdx.x % P2;
    const int tid = threadIdx.x;
    const int m = tid >> 5;            // head
    const int l = tid & 31;
    const int gr = l >> 2, tc = (l & 3) << 1;
    const uint32_t kvb = smem_u32(kv);
    // ldmatrix lane row: lanes 0-7 -> matrix0 rows, 8-15 -> matrix1 rows
    const int lm_row = ((l >> 3) & 1) * 8 + (l & 7);

    if (tid < 4) selw[tid] = g_ridx[(n * P2 + p) * 4 + tid];

    // ---- Q fragments (64q x 32ch per head), pre-scaled by ASCALE ----
    uint32_t qa[4][2][4];
    const __half2 scl = __float2half2_rn(ASCALE);
#pragma unroll
    for (int mi = 0; mi < 4; mi++) {
        int r0 = (mi << 4) + gr;
        int t0 = win_token(n, p, r0);
        int t1 = win_token(n, p, r0 + 8);
#pragma unroll
        for (int kk = 0; kk < 2; kk++) {
            int ch = (m << 5) + (kk << 4) + tc;
            __half2 h0 = *(const __half2*)&g_qkvh[(size_t)t0 * QKVN + ch];
            __half2 h1 = *(const __half2*)&g_qkvh[(size_t)t1 * QKVN + ch];
            __half2 h2 = *(const __half2*)&g_qkvh[(size_t)t0 * QKVN + ch + 8];
            __half2 h3 = *(const __half2*)&g_qkvh[(size_t)t1 * QKVN + ch + 8];
            h0 = __hmul2(h0, scl); h1 = __hmul2(h1, scl);
            h2 = __hmul2(h2, scl); h3 = __hmul2(h3, scl);
            *(__half2*)&qa[mi][kk][0] = h0;
            *(__half2*)&qa[mi][kk][1] = h1;
            *(__half2*)&qa[mi][kk][2] = h2;
            *(__half2*)&qa[mi][kk][3] = h3;
        }
    }

    float oc[4][4][4];
#pragma unroll
    for (int a = 0; a < 4; a++)
#pragma unroll
        for (int b = 0; b < 4; b++)
#pragma unroll
            for (int c = 0; c < 4; c++) oc[a][b][c] = 0.0f;
    float mrow[4][2], lrow[4][2];
#pragma unroll
    for (int a = 0; a < 4; a++) {
        mrow[a][0] = mrow[a][1] = -1e30f;
        lrow[a][0] = lrow[a][1] = 0.0f;
    }

    for (int wl = 0; wl < 4; wl++) {
        __syncthreads();                       // selw ready / prev window done
        int sw = selw[wl];
        int swy = (sw / 7) << 3, swx = (sw % 7) << 3;
        // ---- cooperative load: K||V [64 rows][512 ch] coalesced uint4 ----
#pragma unroll
        for (int i = 0; i < 16; i++) {
            int c = tid + (i << 8);            // 0..4095 uint4 slots
            int row = c >> 6, ch8 = (c & 63) << 3;
            int t = (n * HW + swy + (row >> 3)) * HW + swx + (row & 7);
            *(uint4*)&kv[row * KV_STRIDE + ch8] =
                *(const uint4*)&g_qkvh[(size_t)t * QKVN + 256 + ch8];
        }
        __syncthreads();

        // ---- 4 subchunks of 16 keys, online softmax ----
#pragma unroll
        for (int t = 0; t < 4; t++) {
            int key0 = t << 4;
            uint32_t kb[2][2][2];
#pragma unroll
            for (int ni = 0; ni < 2; ni++)
#pragma unroll
                for (int kk = 0; kk < 2; kk++) {
                    int base = (key0 + (ni << 3) + gr) * KV_STRIDE
                             + (m << 5) + (kk << 4) + tc;
                    kb[ni][kk][0] = *(const uint32_t*)&kv[base];
                    kb[ni][kk][1] = *(const uint32_t*)&kv[base + 8];
                }
            uint32_t paf[4][4];
#pragma unroll
            for (int mi = 0; mi < 4; mi++) {
                float s4[2][4];
#pragma unroll
                for (int ni = 0; ni < 2; ni++)
#pragma unroll
                    for (int j = 0; j < 4; j++) s4[ni][j] = 0.0f;
#pragma unroll
                for (int kk = 0; kk < 2; kk++)
#pragma unroll
                    for (int ni = 0; ni < 2; ni++)
                        mma_f16(s4[ni], qa[mi][kk], kb[ni][kk]);
                float mx0 = fmaxf(fmaxf(s4[0][0], s4[0][1]), fmaxf(s4[1][0], s4[1][1]));
                float mx1 = fmaxf(fmaxf(s4[0][2], s4[0][3]), fmaxf(s4[1][2], s4[1][3]));
#pragma unroll
                for (int off = 1; off <= 2; off <<= 1) {
                    mx0 = fmaxf(mx0, __shfl_xor_sync(~0u, mx0, off));
                    mx1 = fmaxf(mx1, __shfl_xor_sync(~0u, mx1, off));
                }
                float mn0 = fmaxf(mrow[mi][0], mx0);
                float mn1 = fmaxf(mrow[mi][1], mx1);
                float cr0 = fexp(mrow[mi][0] - mn0);
                float cr1 = fexp(mrow[mi][1] - mn1);
                mrow[mi][0] = mn0; mrow[mi][1] = mn1;
                float e00 = fexp(s4[0][0] - mn0), e01 = fexp(s4[0][1] - mn0);
                float e02 = fexp(s4[0][2] - mn1), e03 = fexp(s4[0][3] - mn1);
                float e10 = fexp(s4[1][0] - mn0), e11 = fexp(s4[1][1] - mn0);
                float e12 = fexp(s4[1][2] - mn1), e13 = fexp(s4[1][3] - mn1);
                float sm0 = e00 + e01 + e10 + e11;
                float sm1 = e02 + e03 + e12 + e13;
#pragma unroll
                for (int off = 1; off <= 2; off <<= 1) {
                    sm0 += __shfl_xor_sync(~0u, sm0, off);
                    sm1 += __shfl_xor_sync(~0u, sm1, off);
                }
                lrow[mi][0] = lrow[mi][0] * cr0 + sm0;
                lrow[mi][1] = lrow[mi][1] * cr1 + sm1;
#pragma unroll
                for (int ni = 0; ni < 4; ni++) {
                    oc[mi][ni][0] *= cr0; oc[mi][ni][1] *= cr0;
                    oc[mi][ni][2] *= cr1; oc[mi][ni][3] *= cr1;
                }
                paf[mi][0] = pack_h2(e00, e01);
                paf[mi][1] = pack_h2(e02, e03);
                paf[mi][2] = pack_h2(e10, e11);
                paf[mi][3] = pack_h2(e12, e13);
            }
            // ---- V B-fragments straight from row-major V via ldmatrix.trans
            uint32_t vb[4][2];
#pragma unroll
            for (int ni = 0; ni < 4; ni++) {
                uint32_t addr = kvb +
                    (uint32_t)(((key0 + lm_row) * KV_STRIDE) +
                               256 + (m << 5) + (ni << 3)) * 2;
                ldsm_x2_trans(vb[ni][0], vb[ni][1], addr);
            }
#pragma unroll
            for (int mi = 0; mi < 4; mi++)
#pragma unroll
                for (int ni = 0; ni < 4; ni++)
                    mma_f16(oc[mi][ni], paf[mi], vb[ni]);
        }
    }

    // ---- write O (fp16, pre-lepe) ----
#pragma unroll
    for (int mi = 0; mi < 4; mi++) {
#pragma unroll
        for (int h = 0; h < 2; h++) {
            int row = (mi << 4) + gr + (h << 3);
            int tok = win_token(n, p, row);
            float inv = 1.0f / lrow[mi][h];
#pragma unroll
            for (int ni = 0; ni < 4; ni++) {
                uint32_t pk = pack_h2(oc[mi][ni][h * 2 + 0] * inv,
                                      oc[mi][ni][h * 2 + 1] * inv);
                *(uint32_t*)&g_attnh[(size_t)tok * 256 + (m << 5) + (ni << 3) + tc] = pk;
            }
        }
    }
}

// ---------------- depthwise 5x5 lepe (fp16 v) + add in place ---------------
__global__ __launch_bounds__(256) void lepe_kernel(
    const float* __restrict__ w, const float* __restrict__ b)
{
    int gid = blockIdx.x * 256 + threadIdx.x;   // TOK*64 c4-groups
    int t = gid >> 6;
    int c = (gid & 63) << 2;
    int n = t / 3136, rem = t % 3136, y = rem / 56, x = rem % 56;
    float4 bb = *(const float4*)(b + c);
    float av[4] = {bb.x, bb.y, bb.z, bb.w};
#pragma unroll
    for (int dy = 0; dy < 5; dy++) {
        int yy = y + dy - 2;
        if ((unsigned)yy >= 56u) continue;
#pragma unroll
        for (int dx = 0; dx < 5; dx++) {
            int xx = x + dx - 2;
            if ((unsigned)xx >= 56u) continue;
            uint2 vv2 = *(const uint2*)&g_qkvh[(size_t)((n * 56 + yy) * 56 + xx) * QKVN + 512 + c];
            __half2 vh[2];
            *(uint2*)vh = vv2;
            float4 ww = *(const float4*)(w + (dy * 5 + dx) * 256 + c);
            av[0] = fmaf(__half2float(vh[0].x), ww.x, av[0]);
            av[1] = fmaf(__half2float(vh[0].y), ww.y, av[1]);
            av[2] = fmaf(__half2float(vh[1].x), ww.z, av[2]);
            av[3] = fmaf(__half2float(vh[1].y), ww.w, av[3]);
        }
    }
    uint2 cur2 = *(const uint2*)&g_attnh[(size_t)t * 256 + c];
    __half2 ch[2];
    *(uint2*)ch = cur2;
    uint32_t pk[2];
    pk[0] = pack_h2(__half2float(ch[0].x) + av[0], __half2float(ch[0].y) + av[1]);
    pk[1] = pack_h2(__half2float(ch[1].x) + av[2], __half2float(ch[1].y) + av[3]);
    *(uint2*)&g_attnh[(size_t)t * 256 + c] = *(uint2*)pk;
}

// ---------------- launch ----------------------------------------------------
extern "C" void kernel_launch(void* const* d_in, const int* in_sizes, int n_in,
                              void* d_out, int out_size)
{
    const float* x     = (const float*)d_in[0];
    const float* ln1g  = (const float*)d_in[1];
    const float* ln1b  = (const float*)d_in[2];
    const float* qkvw  = (const float*)d_in[3];
    const float* qkvb  = (const float*)d_in[4];
    const float* lepew = (const float*)d_in[5];
    const float* lepeb = (const float*)d_in[6];
    const float* wow   = (const float*)d_in[7];
    const float* wob   = (const float*)d_in[8];
    const float* ln2g  = (const float*)d_in[9];
    const float* ln2b  = (const float*)d_in[10];
    const float* w1    = (const float*)d_in[11];
    const float* b1    = (const float*)d_in[12];
    const float* w2    = (const float*)d_in[13];
    const float* b2    = (const float*)d_in[14];

    __half *h1h, *qkvh, *attnh, *hidh, *wt;
    float *y1;
    cudaGetSymbolAddress((void**)&h1h,   g_h1h);
    cudaGetSymbolAddress((void**)&qkvh,  g_qkvh);
    cudaGetSymbolAddress((void**)&attnh, g_attnh);
    cudaGetSymbolAddress((void**)&y1,    g_y1);
    cudaGetSymbolAddress((void**)&hidh,  g_hidh);
    cudaGetSymbolAddress((void**)&wt,    g_wt);

    cudaFuncSetAttribute(attn_kernel,
                         cudaFuncAttributeMaxDynamicSharedMemorySize, ATTN_SMEM);

    // weight transpose+convert (smem tile transpose)
    wtrans_kernel<<<dim3(256/32, 768/32),  dim3(256)>>>(qkvw, wt + WT_QKV, 256, 768);
    wtrans_kernel<<<dim3(256/32, 256/32),  dim3(256)>>>(wow,  wt + WT_WO,  256, 256);
    wtrans_kernel<<<dim3(256/32, 1024/32), dim3(256)>>>(w1,   wt + WT_W1,  256, 1024);
    wtrans_kernel<<<dim3(1024/32, 256/32), dim3(256)>>>(w2,   wt + WT_W2,  1024, 256);

    // 1. LN1 -> fp16
    ln_h_kernel<<<3136, 256>>>(x, ln1g, ln1b, h1h);
    // 2. qkv projection (fp16 out only)
    gemm_mma_kernel<<<dim3(6, 196), 256>>>(h1h, wt + WT_QKV, qkvb, nullptr,
                                           nullptr, qkvh, TOK, 768, 256, 0);
    // 3-4. routing (fp16 reads, fp32 accum)
    winmean_kernel<<<392, 512>>>();
    topk_kernel<<<dim3(49, 8), 256>>>();
    // 5. gathered window attention (fp16 HMMA flash, ldmatrix.trans V) -> fp16
    attn_kernel<<<392, 256, ATTN_SMEM>>>();
    // 6. lepe depthwise conv + add in place (fp16)
    lepe_kernel<<<6272, 256>>>(lepew, lepeb);
    // 7. output projection + residual with x -> fp32 y1
    gemm_mma_kernel<<<dim3(2, 196), 256>>>(attnh, wt + WT_WO, wob, x,
                                           y1, nullptr, TOK, 256, 256, 2);
    // 8. LN2 -> fp16
    ln_h_kernel<<<3136, 256>>>(y1, ln2g, ln2b, h1h);
    // 9. MLP up + exact GELU, fp16 out
    gemm_mma_kernel<<<dim3(8, 196), 256>>>(h1h, wt + WT_W1, b1, nullptr,
                                           nullptr, hidh, TOK, 1024, 256, 1);
    // 10. MLP down + residual -> d_out
    gemm_mma_kernel<<<dim3(2, 196), 256>>>(hidh, wt + WT_W2, b2, y1,
                                           (float*)d_out, nullptr, TOK, 256, 1024, 2);
}